// round 15
// baseline (speedup 1.0000x reference)
#include <cuda_runtime.h>
#include <cuda_bf16.h>
#include <cstdint>
#include <cstdio>

#define S 2048
#define Dm 2048
#define Hh 16
#define HD 128
#define CACHE 408
#define RECENT 204
#define PENALTY 0.4f
#define NEG_MIN_F (-3.4028234663852886e38f)
#define SQRT_HD_F 11.313708498984761f
#define WARM_START 288

#define G_ALO 20480
#define G_BHI 40960
#define G_BLO 51200
#define G_STAGE 61440
#define G_SMEM (3 * G_STAGE)
#define PV_SMEM 81920

// ---------------- scratch ----------------
__device__ float g_QKV[3 * Hh * S * HD];      // Q | K | V
__device__ float g_scores[Hh * S * S];
__device__ float g_rownorm[Hh * S];
__device__ float g_rowsum[Hh * S];
__device__ int   g_evict[Hh * S];
__device__ __nv_bfloat16 g_HSh[Dm * Dm], g_HSl[Dm * Dm];
__device__ __nv_bfloat16 g_Wsp[8 * Dm * Dm];  // wqh,wql,wkh,wkl,wvh,wvl,woh,wol
__device__ __nv_bfloat16 g_Qbh[Hh * S * HD], g_Qbl[Hh * S * HD];
__device__ __nv_bfloat16 g_Kbh[Hh * S * HD], g_Kbl[Hh * S * HD];
__device__ __nv_bfloat16 g_VTh[Hh * HD * S], g_VTl[Hh * HD * S];
__device__ __nv_bfloat16 g_AOh[S * Dm], g_AOl[S * Dm];

// ---------------- helpers ----------------
__device__ __forceinline__ uint32_t smem_u32(const void* p) {
    uint32_t a;
    asm("{ .reg .u64 t; cvta.to.shared.u64 t, %1; cvt.u32.u64 %0, t; }" : "=r"(a) : "l"(p));
    return a;
}
__device__ __forceinline__ void sts128(uint32_t addr, uint4 v) {
    asm volatile("st.shared.v4.b32 [%0], {%1,%2,%3,%4};"
                 :: "r"(addr), "r"(v.x), "r"(v.y), "r"(v.z), "r"(v.w) : "memory");
}
__device__ __forceinline__ void cpa16(uint32_t dst, const void* src) {
    asm volatile("cp.async.cg.shared.global [%0], [%1], 16;" :: "r"(dst), "l"(src));
}
__device__ __forceinline__ void ldsm4(uint32_t addr, uint32_t* r) {
    asm volatile("ldmatrix.sync.aligned.m8n8.x4.shared.b16 {%0,%1,%2,%3}, [%4];"
                 : "=r"(r[0]), "=r"(r[1]), "=r"(r[2]), "=r"(r[3]) : "r"(addr));
}
__device__ __forceinline__ void mma16816(float* d, const uint32_t* a, uint32_t b0, uint32_t b1) {
    asm volatile(
        "mma.sync.aligned.m16n8k16.row.col.f32.bf16.bf16.f32 "
        "{%0,%1,%2,%3},{%4,%5,%6,%7},{%8,%9},{%0,%1,%2,%3};"
        : "+f"(d[0]), "+f"(d[1]), "+f"(d[2]), "+f"(d[3])
        : "r"(a[0]), "r"(a[1]), "r"(a[2]), "r"(a[3]), "r"(b0), "r"(b1));
}
__device__ __forceinline__ void split2(float x, float y, uint32_t& hi, uint32_t& lo) {
    __nv_bfloat162 hb = __floats2bfloat162_rn(x, y);
    float2 hf = __bfloat1622float2(hb);
    __nv_bfloat162 lb = __floats2bfloat162_rn(x - hf.x, y - hf.y);
    hi = *(uint32_t*)&hb;
    lo = *(uint32_t*)&lb;
}

// 3-sweep inner compute
template <int ALO, int BHI, int BLO>
__device__ __forceinline__ void comp_chunk(
    uint32_t base, uint32_t aAddrBase, uint32_t bAddrBase, float (*acc)[8][4])
{
#pragma unroll
    for (int s = 0; s < 2; s++) {
        uint32_t ah[2][4], al2[2][4], bfr[4][4];
#pragma unroll
        for (int mt = 0; mt < 2; mt++) {
            uint32_t ad = base + aAddrBase + mt * 1280 + s * 32;
            ldsm4(ad, ah[mt]);
            ldsm4(ad + ALO, al2[mt]);
        }
#pragma unroll
        for (int pr = 0; pr < 4; pr++)
            ldsm4(base + BHI + bAddrBase + pr * 1280 + s * 32, bfr[pr]);
#pragma unroll
        for (int pr = 0; pr < 4; pr++)
#pragma unroll
            for (int mt = 0; mt < 2; mt++) {
                mma16816(acc[mt][2 * pr], ah[mt], bfr[pr][0], bfr[pr][1]);
                mma16816(acc[mt][2 * pr + 1], ah[mt], bfr[pr][2], bfr[pr][3]);
            }
#pragma unroll
        for (int pr = 0; pr < 4; pr++)
#pragma unroll
            for (int mt = 0; mt < 2; mt++) {
                mma16816(acc[mt][2 * pr], al2[mt], bfr[pr][0], bfr[pr][1]);
                mma16816(acc[mt][2 * pr + 1], al2[mt], bfr[pr][2], bfr[pr][3]);
            }
#pragma unroll
        for (int pr = 0; pr < 4; pr++)
            ldsm4(base + BLO + bAddrBase + pr * 1280 + s * 32, bfr[pr]);
#pragma unroll
        for (int pr = 0; pr < 4; pr++)
#pragma unroll
            for (int mt = 0; mt < 2; mt++) {
                mma16816(acc[mt][2 * pr], ah[mt], bfr[pr][0], bfr[pr][1]);
                mma16816(acc[mt][2 * pr + 1], ah[mt], bfr[pr][2], bfr[pr][3]);
            }
    }
}

// ---------------- big-tile cp.async GEMM ----------------
// MODE 0: plain fp32 C. MODE 1: QKV batched (z = weight index), split-head.
// MODE 2: logits (causal + scale, z = head)
template <int MODE>
__global__ void __launch_bounds__(512, 1) cp_gemm(
    const __nv_bfloat16* __restrict__ Ah, const __nv_bfloat16* __restrict__ Al,
    const __nv_bfloat16* __restrict__ Bh, const __nv_bfloat16* __restrict__ Bl,
    float* __restrict__ C,
    int Kd, int lda, int ldb, int ldc,
    size_t az, size_t bz, size_t cz)
{
    const int m0 = blockIdx.y * 256, n0 = blockIdx.x * 128, z = blockIdx.z;
    if (MODE == 2 && n0 >= m0 + 256) return;
    extern __shared__ char smem[];
    const uint32_t sb = smem_u32(smem);
    const int tid = threadIdx.x, lane = tid & 31, warp = tid >> 5;
    const int arow = tid & 255, aseg = tid >> 8;
    const int brow = tid >> 2, bq = tid & 3;

    const __nv_bfloat16* Ahb = Ah + (size_t)z * az;
    const __nv_bfloat16* Alb = Al + (size_t)z * az;
    const __nv_bfloat16* Bhb = Bh + (size_t)z * bz;
    const __nv_bfloat16* Blb = Bl + (size_t)z * bz;
    const int nch = Kd >> 5;

    float acc[2][8][4];
#pragma unroll
    for (int a = 0; a < 2; a++)
#pragma unroll
        for (int b = 0; b < 8; b++)
#pragma unroll
            for (int e = 0; e < 4; e++) acc[a][b][e] = 0.f;

    auto issue = [&](int c, int stg) {
        const int k0 = c << 5;
        const uint32_t st = sb + stg * G_STAGE;
        const uint32_t da = st + arow * 80 + aseg * 32;
        const __nv_bfloat16* pa = Ahb + (size_t)(m0 + arow) * lda + k0 + aseg * 16;
        cpa16(da, pa);               cpa16(da + 16, pa + 8);
        const __nv_bfloat16* pl = Alb + (size_t)(m0 + arow) * lda + k0 + aseg * 16;
        cpa16(da + G_ALO, pl);       cpa16(da + G_ALO + 16, pl + 8);
        const uint32_t db = st + brow * 80 + bq * 16;
        cpa16(db + G_BHI, Bhb + (size_t)(n0 + brow) * ldb + k0 + bq * 8);
        cpa16(db + G_BLO, Blb + (size_t)(n0 + brow) * ldb + k0 + bq * 8);
        asm volatile("cp.async.commit_group;");
    };

    const int warpM = (warp >> 1) * 32, warpN = (warp & 1) * 64;
    const uint32_t aAddrBase = (warpM + (lane & 15)) * 80 + (lane >> 4) * 16;
    const uint32_t bAddrBase = (warpN + ((lane >> 4) << 3) + (lane & 7)) * 80 + ((lane >> 3) & 1) * 16;

    issue(0, 0);
    if (nch > 1) issue(1, 1);
    int st = 0;
    for (int c = 0; c < nch; c++) {
        if (c + 1 < nch) asm volatile("cp.async.wait_group 1;");
        else             asm volatile("cp.async.wait_group 0;");
        __syncthreads();
        if (c + 2 < nch) {
            int stn = st + 2; if (stn >= 3) stn -= 3;
            issue(c + 2, stn);
        }
        comp_chunk<G_ALO, G_BHI, G_BLO>(sb + st * G_STAGE, aAddrBase, bAddrBase, acc);
        if (++st == 3) st = 0;
    }

    const int erow = lane >> 2, ecol = (lane & 3) * 2;
#pragma unroll
    for (int mt = 0; mt < 2; mt++) {
        int r0 = m0 + warpM + mt * 16 + erow;
        int r1 = r0 + 8;
#pragma unroll
        for (int nt = 0; nt < 8; nt++) {
            int c0 = n0 + warpN + nt * 8 + ecol;
            float d0 = acc[mt][nt][0], d1 = acc[mt][nt][1];
            float d2 = acc[mt][nt][2], d3 = acc[mt][nt][3];
            if (MODE == 0) {
                *(float2*)&C[(size_t)r0 * ldc + c0] = make_float2(d0, d1);
                *(float2*)&C[(size_t)r1 * ldc + c0] = make_float2(d2, d3);
            } else if (MODE == 1) {
                float* Cb = C + (size_t)z * cz;
                int hd = c0 >> 7, cl = c0 & 127;
                *(float2*)&Cb[((size_t)hd * S + r0) * HD + cl] = make_float2(d0, d1);
                *(float2*)&Cb[((size_t)hd * S + r1) * HD + cl] = make_float2(d2, d3);
            } else {
                const float iv = 1.f / SQRT_HD_F;
                float* Cb = C + (size_t)z * cz;
                float v0 = (c0 <= r0) ? d0 * iv : NEG_MIN_F;
                float v1 = (c0 + 1 <= r0) ? d1 * iv : NEG_MIN_F;
                float v2 = (c0 <= r1) ? d2 * iv : NEG_MIN_F;
                float v3 = (c0 + 1 <= r1) ? d3 * iv : NEG_MIN_F;
                *(float2*)&Cb[(size_t)r0 * ldc + c0] = make_float2(v0, v1);
                *(float2*)&Cb[(size_t)r1 * ldc + c0] = make_float2(v2, v3);
            }
        }
    }
}

// ---------------- PV GEMM (register A-path, evict mask only, heavy-first) ----------------
__global__ void __launch_bounds__(256, 1) pv_gemm(
    const float* __restrict__ Af,
    const __nv_bfloat16* __restrict__ Bh, const __nv_bfloat16* __restrict__ Bl,
    __nv_bfloat16* __restrict__ Coh, __nv_bfloat16* __restrict__ Col,
    int lda, int ldb,
    size_t az, size_t bz,
    const int* __restrict__ evBase, const float* __restrict__ rsBase)
{
    const int m0 = (15 - blockIdx.y) * 128, n0 = 0, z = blockIdx.z;
    extern __shared__ char smem[];
    const uint32_t sb = smem_u32(smem);
    const int tid = threadIdx.x, lane = tid & 31, warp = tid >> 5;
    const int arow = tid & 127, aseg = tid >> 7;

    const float* Afb = Af + (size_t)z * az;
    const int* evp = evBase + (size_t)z * S;
    const __nv_bfloat16* Bhb = Bh + (size_t)z * bz;
    const __nv_bfloat16* Blb = Bl + (size_t)z * bz;

    const int nch = (m0 + 128) >> 5;

    float acc[2][8][4];
#pragma unroll
    for (int a = 0; a < 2; a++)
#pragma unroll
        for (int b = 0; b < 8; b++)
#pragma unroll
            for (int e = 0; e < 4; e++) acc[a][b][e] = 0.f;

    uint4 rah[2], ral[2], rbh[2], rbl[2];

    auto ldg = [&](int k0) {
        const int kb = k0 + aseg * 16;
        const float* p = Afb + (size_t)(m0 + arow) * lda + kb;
        float f[16];
#pragma unroll
        for (int q = 0; q < 4; q++) *(float4*)&f[q * 4] = *(const float4*)(p + q * 4);
        const int r = m0 + arow;
        const int4* e4 = (const int4*)(evp + kb);
#pragma unroll
        for (int q = 0; q < 4; q++) {
            int4 e = e4[q];
            if (e.x < r) f[q * 4 + 0] = 0.f;
            if (e.y < r) f[q * 4 + 1] = 0.f;
            if (e.z < r) f[q * 4 + 2] = 0.f;
            if (e.w < r) f[q * 4 + 3] = 0.f;
        }
        uint32_t h[8], l[8];
#pragma unroll
        for (int q = 0; q < 8; q++) split2(f[q * 2], f[q * 2 + 1], h[q], l[q]);
        rah[0] = make_uint4(h[0], h[1], h[2], h[3]); rah[1] = make_uint4(h[4], h[5], h[6], h[7]);
        ral[0] = make_uint4(l[0], l[1], l[2], l[3]); ral[1] = make_uint4(l[4], l[5], l[6], l[7]);
        const uint4* qh = (const uint4*)(Bhb + (size_t)(n0 + arow) * ldb + kb);
        rbh[0] = qh[0]; rbh[1] = qh[1];
        const uint4* ql = (const uint4*)(Blb + (size_t)(n0 + arow) * ldb + kb);
        rbl[0] = ql[0]; rbl[1] = ql[1];
    };
    auto sts = [&](int buf) {
        uint32_t b = sb + buf * 40960 + arow * 80 + aseg * 32;
        sts128(b, rah[0]);          sts128(b + 16, rah[1]);
        sts128(b + 10240, ral[0]);  sts128(b + 10240 + 16, ral[1]);
        sts128(b + 20480, rbh[0]);  sts128(b + 20480 + 16, rbh[1]);
        sts128(b + 30720, rbl[0]);  sts128(b + 30720 + 16, rbl[1]);
    };

    const int warpM = (warp >> 1) * 32, warpN = (warp & 1) * 64;
    const uint32_t aAddrBase = (warpM + (lane & 15)) * 80 + (lane >> 4) * 16;
    const uint32_t bAddrBase = (warpN + ((lane >> 4) << 3) + (lane & 7)) * 80 + ((lane >> 3) & 1) * 16;

    ldg(0);
    sts(0);
    __syncthreads();
    for (int c = 0; c < nch; c++) {
        if (c + 1 < nch) ldg((c + 1) << 5);
        comp_chunk<10240, 20480, 30720>(sb + (c & 1) * 40960, aAddrBase, bAddrBase, acc);
        if (c + 1 < nch) sts((c + 1) & 1);
        __syncthreads();
    }

    const int erow = lane >> 2, ecol = (lane & 3) * 2;
#pragma unroll
    for (int mt = 0; mt < 2; mt++) {
        int r0 = m0 + warpM + mt * 16 + erow;
        int r1 = r0 + 8;
        float inv0 = 1.f / rsBase[(size_t)z * S + r0];
        float inv1 = 1.f / rsBase[(size_t)z * S + r1];
#pragma unroll
        for (int nt = 0; nt < 8; nt++) {
            int c0 = n0 + warpN + nt * 8 + ecol;
            float v0 = acc[mt][nt][0] * inv0, v1 = acc[mt][nt][1] * inv0;
            float v2 = acc[mt][nt][2] * inv1, v3 = acc[mt][nt][3] * inv1;
            uint32_t h0, l0, h1, l1;
            split2(v0, v1, h0, l0);
            split2(v2, v3, h1, l1);
            size_t o0 = (size_t)r0 * Dm + z * HD + c0;
            size_t o1 = (size_t)r1 * Dm + z * HD + c0;
            *(uint32_t*)&Coh[o0] = h0; *(uint32_t*)&Col[o0] = l0;
            *(uint32_t*)&Coh[o1] = h1; *(uint32_t*)&Col[o1] = l1;
        }
    }
}

// ---------------- fp32 -> bf16 hi/lo split (single) ----------------
__global__ void __launch_bounds__(256) split_kernel(
    const float* __restrict__ x, __nv_bfloat16* __restrict__ hi, __nv_bfloat16* __restrict__ lo)
{
    int i = (blockIdx.x * 256 + threadIdx.x) * 8;
    float f[8];
    *(float4*)&f[0] = *(const float4*)(x + i);
    *(float4*)&f[4] = *(const float4*)(x + i + 4);
    uint32_t h[4], l[4];
#pragma unroll
    for (int q = 0; q < 4; q++) split2(f[q * 2], f[q * 2 + 1], h[q], l[q]);
    *(uint4*)(hi + i) = make_uint4(h[0], h[1], h[2], h[3]);
    *(uint4*)(lo + i) = make_uint4(l[0], l[1], l[2], l[3]);
}

// ---------------- batched weight split (wq/wk/wv by z) ----------------
__global__ void __launch_bounds__(256) split3_kernel(
    const float* __restrict__ w0, const float* __restrict__ w1, const float* __restrict__ w2,
    __nv_bfloat16* __restrict__ base)
{
    const int z = blockIdx.z;
    const float* x = (z == 0) ? w0 : (z == 1) ? w1 : w2;
    __nv_bfloat16* hi = base + (size_t)z * 2 * Dm * Dm;
    __nv_bfloat16* lo = hi + (size_t)Dm * Dm;
    int i = (blockIdx.x * 256 + threadIdx.x) * 8;
    float f[8];
    *(float4*)&f[0] = *(const float4*)(x + i);
    *(float4*)&f[4] = *(const float4*)(x + i + 4);
    uint32_t h[4], l[4];
#pragma unroll
    for (int q = 0; q < 4; q++) split2(f[q * 2], f[q * 2 + 1], h[q], l[q]);
    *(uint4*)(hi + i) = make_uint4(h[0], h[1], h[2], h[3]);
    *(uint4*)(lo + i) = make_uint4(l[0], l[1], l[2], l[3]);
}

// ---------------- RoPE (fp32 in -> bf16 split out) ----------------
__global__ void __launch_bounds__(64) rope_split_kernel(const int* __restrict__ pos_ids)
{
    int hs = blockIdx.x;
    int h = hs / S, s = hs % S;
    int d = threadIdx.x;
    float posf = (float)pos_ids[s];
    float invf = powf(10000.f, -((float)d) / 64.f);
    float fr = posf * invf;
    float c = cosf(fr), sn = sinf(fr);
    size_t base = ((size_t)h * S + s) * HD;
    const float* Q = g_QKV;
    const float* K = g_QKV + (size_t)Hh * S * HD;
    float q1 = Q[base + d], q2 = Q[base + d + 64];
    float k1 = K[base + d], k2 = K[base + d + 64];
    float qa = q1 * c - q2 * sn, qb = q2 * c + q1 * sn;
    float ka = k1 * c - k2 * sn, kb = k2 * c + k1 * sn;
#define WR(arr_h, arr_l, off, v) do { \
        __nv_bfloat16 _hb = __float2bfloat16_rn(v); \
        arr_h[base + (off)] = _hb; \
        arr_l[base + (off)] = __float2bfloat16_rn((v) - __bfloat162float(_hb)); } while (0)
    WR(g_Qbh, g_Qbl, d, qa);
    WR(g_Qbh, g_Qbl, d + 64, qb);
    WR(g_Kbh, g_Kbl, d, ka);
    WR(g_Kbh, g_Kbl, d + 64, kb);
#undef WR
}

// ---------------- V transpose + split ----------------
__global__ void __launch_bounds__(256) vtrans_kernel()
{
    __shared__ float tile[32][33];
    int h = blockIdx.z, s0 = blockIdx.x * 32, d0 = blockIdx.y * 32;
    int tx = threadIdx.x & 31, ty = threadIdx.x >> 5;
    const float* Vb = g_QKV + (size_t)2 * Hh * S * HD + (size_t)h * S * HD;
#pragma unroll
    for (int i = 0; i < 4; i++)
        tile[ty * 4 + i][tx] = Vb[(size_t)(s0 + ty * 4 + i) * HD + d0 + tx];
    __syncthreads();
#pragma unroll
    for (int i = 0; i < 4; i++) {
        int d = d0 + ty * 4 + i;
        float v = tile[tx][ty * 4 + i];
        __nv_bfloat16 hb = __float2bfloat16_rn(v);
        g_VTh[((size_t)h * HD + d) * S + s0 + tx] = hb;
        g_VTl[((size_t)h * HD + d) * S + s0 + tx] = __float2bfloat16_rn(v - __bfloat162float(hb));
    }
}

// ---------------- softmax: triangular reads, exp-skip branches, full zero writes ----------------
__global__ void __launch_bounds__(256) softmax_kernel()
{
    int r = blockIdx.x, h = blockIdx.y, tid = threadIdx.x;
    float* row = g_scores + ((size_t)h * S + r) * S;
    float4* row4 = (float4*)row;
    const int n = r + 1;
    const int nv = (r >> 2) + 1;     // float4s containing any valid data
    __shared__ float sred[9];

    float4 v0 = make_float4(NEG_MIN_F, NEG_MIN_F, NEG_MIN_F, NEG_MIN_F), v1 = v0;
    if (tid < nv) v0 = row4[tid];
    if (tid + 256 < nv) v1 = row4[tid + 256];
    const int p0 = tid * 4, p1 = 1024 + tid * 4;
    float mx = NEG_MIN_F;
    if (p0 < n) {
        mx = fmaxf(mx, v0.x);
        mx = fmaxf(mx, (p0 + 1 < n) ? v0.y : NEG_MIN_F);
        mx = fmaxf(mx, (p0 + 2 < n) ? v0.z : NEG_MIN_F);
        mx = fmaxf(mx, (p0 + 3 < n) ? v0.w : NEG_MIN_F);
    }
    if (p1 < n) {
        mx = fmaxf(mx, v1.x);
        mx = fmaxf(mx, (p1 + 1 < n) ? v1.y : NEG_MIN_F);
        mx = fmaxf(mx, (p1 + 2 < n) ? v1.z : NEG_MIN_F);
        mx = fmaxf(mx, (p1 + 3 < n) ? v1.w : NEG_MIN_F);
    }
#pragma unroll
    for (int o = 16; o > 0; o >>= 1) mx = fmaxf(mx, __shfl_xor_sync(0xffffffffu, mx, o));
    if ((tid & 31) == 0) sred[tid >> 5] = mx;
    __syncthreads();
    if (tid == 0) { float m = sred[0]; for (int i = 1; i < 8; i++) m = fmaxf(m, sred[i]); sred[8] = m; }
    __syncthreads();
    mx = sred[8];
    __syncthreads();

    float4 e0 = make_float4(0.f, 0.f, 0.f, 0.f), e1 = e0;
    float loc = 0.f;
    if (p0 < n) {
        e0.x = __expf(v0.x - mx);
        e0.y = (p0 + 1 < n) ? __expf(v0.y - mx) : 0.f;
        e0.z = (p0 + 2 < n) ? __expf(v0.z - mx) : 0.f;
        e0.w = (p0 + 3 < n) ? __expf(v0.w - mx) : 0.f;
        loc += e0.x + e0.y + e0.z + e0.w;
    }
    if (p1 < n) {
        e1.x = __expf(v1.x - mx);
        e1.y = (p1 + 1 < n) ? __expf(v1.y - mx) : 0.f;
        e1.z = (p1 + 2 < n) ? __expf(v1.z - mx) : 0.f;
        e1.w = (p1 + 3 < n) ? __expf(v1.w - mx) : 0.f;
        loc += e1.x + e1.y + e1.z + e1.w;
    }
#pragma unroll
    for (int o = 16; o > 0; o >>= 1) loc += __shfl_xor_sync(0xffffffffu, loc, o);
    if ((tid & 31) == 0) sred[tid >> 5] = loc;
    __syncthreads();
    if (tid == 0) {
        float s2 = 0.f;
        for (int i = 0; i < 8; i++) s2 += sred[i];
        g_rownorm[h * S + r] = s2;
        g_rowsum[h * S + r] = s2;
    }

    row4[tid] = e0;
    row4[tid + 256] = e1;
}

// ---------------- eviction scan: 6-deep row pipeline, early load issue ----------------
__global__ void __launch_bounds__(256) scan_kernel()
{
    const int h = blockIdx.x, tid = threadIdx.x;
    const int lane = tid & 31, warp = tid >> 5;
    const float* sc = g_scores + (size_t)h * S * S;
    __shared__ float coefEff[CACHE];
    __shared__ uint4 sRed[2][8];
    __shared__ float sInit[8];

#pragma unroll
    for (int i = 0; i < 8; i++) g_evict[h * S + tid + i * 256] = 0x7fffffff;

    for (int i = tid; i < CACHE; i += 256)
        coefEff[i] = powf(PENALTY, (float)(CACHE - 1 - i)) / g_rownorm[h * S + i];
    __syncthreads();

    float sel[8];
#pragma unroll
    for (int i = 0; i < 8; i++) sel[i] = 0.f;

    for (int rrow = WARM_START; rrow < CACHE; rrow++) {
        float cf = coefEff[rrow];
        if (cf != 0.f) {
            const float* rp = sc + (size_t)rrow * S + tid;
            sel[0] = fmaf(cf, rp[0],   sel[0]);
            sel[1] = fmaf(cf, rp[256], sel[1]);
        }
    }

    // 6-deep register row pipeline: r = row t, n1..n5 = t+1..t+5
    float r[8], n1[8], n2[8], n3[8], n4[8], n5[8];
    {
        const float* rp = sc + (size_t)CACHE * S + tid;
#pragma unroll
        for (int i = 0; i < 8; i++) r[i] = rp[i * 256];
        const float* q1 = sc + (size_t)(CACHE + 1) * S + tid;
#pragma unroll
        for (int i = 0; i < 8; i++) n1[i] = q1[i * 256];
        const float* q2 = sc + (size_t)(CACHE + 2) * S + tid;
#pragma unroll
        for (int i = 0; i < 8; i++) n2[i] = q2[i * 256];
        const float* q3 = sc + (size_t)(CACHE + 3) * S + tid;
#pragma unroll
        for (int i = 0; i < 8; i++) n3[i] = q3[i * 256];
        const float* q4 = sc + (size_t)(CACHE + 4) * S + tid;
#pragma unroll
        for (int i = 0; i < 8; i++) n4[i] = q4[i * 256];
        const float* q5 = sc + (size_t)(CACHE + 5) * S + tid;
#pragma unroll
        for (int i = 0; i < 8; i++) n5[i] = q5[i * 256];
    }
    float tot;
    {
        float loc = 0.f;
#pragma unroll
        for (int i = 0; i < 8; i++) loc += r[i];
#pragma unroll
        for (int o = 16; o > 0; o >>= 1) loc += __shfl_xor_sync(0xffffffffu, loc, o);
        if (lane == 0) sInit[warp] = loc;
        __syncthreads();
        float s2 = 0.f;
#pragma unroll
        for (int w = 0; w < 8; w++) s2 += sInit[w];
        tot = s2;
    }

    for (int t = CACHE; t < S - 1; t++) {
        const int buf = t & 1;
        const int lim = t - RECENT;
        const float inv = 1.0f / tot;
        unsigned long long key = ~0ull;
        float pay = 0.f, sg = 0.f;
#pragma unroll
        for (int i = 0; i < 8; i++) {
            bool keep = (sel[i] <= 1.0e30f);
            float c = keep ? r[i] : 0.f;
            float ns = __fadd_rn(__fmul_rn(PENALTY, sel[i]), __fmul_rn(c, inv));
            sel[i] = ns;
            sg += keep ? n1[i] : 0.f;
            int p = tid + (i << 8);
            if (p <= lim) {
                unsigned long long k2 =
                    ((unsigned long long)__float_as_uint(ns) << 32) | (unsigned)p;
                if (k2 < key) { key = k2; pay = n1[i]; }
            }
        }
        // shift + issue next row loads EARLY (before reductions) -> ~4.3 steps of slack
#pragma unroll
        for (int i = 0; i < 8; i++) {
            r[i] = n1[i]; n1[i] = n2[i]; n2[i] = n3[i]; n3[i] = n4[i]; n4[i] = n5[i];
        }
        if (t + 6 < S) {
            const float* rp = sc + (size_t)(t + 6) * S + tid;
#pragma unroll
            for (int i = 0; i < 8; i++) n5[i] = rp[i * 256];
        }

        float wsum = sg;
#pragma unroll
        for (int o = 16; o > 0; o >>= 1) wsum += __shfl_xor_sync(0xffffffffu, wsum, o);
        uint32_t lv = (uint32_t)(key >> 32), lp = (uint32_t)key;
        uint32_t vmin = __reduce_min_sync(0xffffffffu, lv);
        uint32_t pmin = __reduce_min_sync(0xffffffffu, (lv == vmin) ? lp : 0xffffffffu);
        float wpay = __shfl_sync(0xffffffffu, pay, (int)(pmin & 31));
        if (lane == 0)
            sRed[buf][warp] = make_uint4(vmin, pmin, __float_as_uint(wsum), __float_as_uint(wpay));
        __syncthreads();
        uint4 q0 = sRed[buf][0];
        unsigned long long gk = ((unsigned long long)q0.x << 32) | q0.y;
        float gs = __uint_as_float(q0.z), gpay = __uint_as_float(q0.w);
#pragma unroll
        for (int w = 1; w < 8; w++) {
            uint4 q = sRed[buf][w];
            unsigned long long kk = ((unsigned long long)q.x << 32) | q.y;
            gs += __uint_as_float(q.z);
            if (kk < gk) { gk = kk; gpay = __uint_as_float(q.w); }
        }
        int mpos = (int)(gk & 0xffffffffu);
        tot = gs - gpay;

        if (tid == 0) g_rowsum[h * S + t + 1] = tot;
        if ((mpos & 255) == tid) {
            sel[mpos >> 8] = __int_as_float(0x7f800000);
            g_evict[h * S + mpos] = t;
        }
    }
}

// ---------------- launch ----------------
extern "C" void kernel_launch(void* const* d_in, const int* in_sizes, int n_in,
                              void* d_out, int out_size)
{
    (void)in_sizes; (void)n_in; (void)out_size;
    const float* hs  = (const float*)d_in[0];
    const int*   pos = (const int*)d_in[2];
    const float* wq  = (const float*)d_in[3];
    const float* wk  = (const float*)d_in[4];
    const float* wv  = (const float*)d_in[5];
    const float* wo  = (const float*)d_in[6];
    float* out = (float*)d_out;

    float *pQKV, *pS, *pRs;
    int* pEv;
    __nv_bfloat16 *pHSh, *pHSl, *pW, *pQh, *pQl, *pKh, *pKl, *pVTh, *pVTl, *pAOh, *pAOl;
    cudaGetSymbolAddress((void**)&pQKV, g_QKV);
    cudaGetSymbolAddress((void**)&pS,   g_scores);
    cudaGetSymbolAddress((void**)&pRs,  g_rowsum);
    cudaGetSymbolAddress((void**)&pEv,  g_evict);
    cudaGetSymbolAddress((void**)&pHSh, g_HSh);
    cudaGetSymbolAddress((void**)&pHSl, g_HSl);
    cudaGetSymbolAddress((void**)&pW,   g_Wsp);
    cudaGetSymbolAddress((void**)&pQh,  g_Qbh);
    cudaGetSymbolAddress((void**)&pQl,  g_Qbl);
    cudaGetSymbolAddress((void**)&pKh,  g_Kbh);
    cudaGetSymbolAddress((void**)&pKl,  g_Kbl);
    cudaGetSymbolAddress((void**)&pVTh, g_VTh);
    cudaGetSymbolAddress((void**)&pVTl, g_VTl);
    cudaGetSymbolAddress((void**)&pAOh, g_AOh);
    cudaGetSymbolAddress((void**)&pAOl, g_AOl);

    const size_t DD = (size_t)Dm * Dm;
    __nv_bfloat16* woh = pW + 6 * DD; __nv_bfloat16* wol = pW + 7 * DD;

    cudaFuncSetAttribute(cp_gemm<0>, cudaFuncAttributeMaxDynamicSharedMemorySize, G_SMEM);
    cudaFuncSetAttribute(cp_gemm<1>, cudaFuncAttributeMaxDynamicSharedMemorySize, G_SMEM);
    cudaFuncSetAttribute(cp_gemm<2>, cudaFuncAttributeMaxDynamicSharedMemorySize, G_SMEM);
    cudaFuncSetAttribute(pv_gemm,    cudaFuncAttributeMaxDynamicSharedMemorySize, PV_SMEM);

    const int splitGrid = (int)(DD / (256 * 8));
    split_kernel<<<splitGrid, 256>>>(hs, pHSh, pHSl);
    split3_kernel<<<dim3(splitGrid, 1, 3), 256>>>(wq, wk, wv, pW);
    split_kernel<<<splitGrid, 256>>>(wo, woh, wol);
    // slot 4 (profiled): merged QKV projection
    cp_gemm<1><<<dim3(16, 8, 3), 512, G_SMEM>>>(pHSh, pHSl, pW, pW + DD, pQKV,
        Dm, Dm, Dm, Dm, 0, 2 * DD, (size_t)Hh * S * HD);
    rope_split_kernel<<<Hh * S, 64>>>(pos);
    vtrans_kernel<<<dim3(S / 32, HD / 32, Hh), 256>>>();
    cp_gemm<2><<<dim3(16, 8, Hh), 512, G_SMEM>>>(pQh, pQl, pKh, pKl, pS,
        HD, HD, HD, S, (size_t)S * HD, (size_t)S * HD, (size_t)S * S);
    softmax_kernel<<<dim3(S, Hh), 256>>>();
    scan_kernel<<<Hh, 256>>>();
    pv_gemm<<<dim3(1, 16, Hh), 256, PV_SMEM>>>(pS, pVTh, pVTl, pAOh, pAOl,
        S, S, (size_t)S * S, (size_t)HD * S, pEv, pRs);
    cp_gemm<0><<<dim3(16, 8, 1), 512, G_SMEM>>>(pAOh, pAOl, woh, wol, out,
        Dm, Dm, Dm, Dm, 0, 0, 0);
}

// round 16
// speedup vs baseline: 1.0797x; 1.0797x over previous
#include <cuda_runtime.h>
#include <cuda_bf16.h>
#include <cstdint>
#include <cstdio>

#define S 2048
#define Dm 2048
#define Hh 16
#define HD 128
#define CACHE 408
#define RECENT 204
#define PENALTY 0.4f
#define NEG_MIN_F (-3.4028234663852886e38f)
#define SQRT_HD_F 11.313708498984761f
#define WARM_START 288

#define G_ALO 20480
#define G_BHI 40960
#define G_BLO 51200
#define G_STAGE 61440
#define G_SMEM (3 * G_STAGE)
#define PV_SMEM 81920

// ---------------- scratch ----------------
__device__ float g_QKV[3 * Hh * S * HD];      // Q | K | V
__device__ float g_scores[Hh * S * S];
__device__ float g_rownorm[Hh * S];
__device__ float g_rowsum[Hh * S];
__device__ int   g_evict[Hh * S];
__device__ __nv_bfloat16 g_HSh[Dm * Dm], g_HSl[Dm * Dm];
__device__ __nv_bfloat16 g_Wsp[8 * Dm * Dm];  // wqh,wql,wkh,wkl,wvh,wvl,woh,wol
__device__ __nv_bfloat16 g_Qbh[Hh * S * HD], g_Qbl[Hh * S * HD];
__device__ __nv_bfloat16 g_Kbh[Hh * S * HD], g_Kbl[Hh * S * HD];
__device__ __nv_bfloat16 g_VTh[Hh * HD * S], g_VTl[Hh * HD * S];
__device__ __nv_bfloat16 g_AOh[S * Dm], g_AOl[S * Dm];

// ---------------- helpers ----------------
__device__ __forceinline__ uint32_t smem_u32(const void* p) {
    uint32_t a;
    asm("{ .reg .u64 t; cvta.to.shared.u64 t, %1; cvt.u32.u64 %0, t; }" : "=r"(a) : "l"(p));
    return a;
}
__device__ __forceinline__ void sts128(uint32_t addr, uint4 v) {
    asm volatile("st.shared.v4.b32 [%0], {%1,%2,%3,%4};"
                 :: "r"(addr), "r"(v.x), "r"(v.y), "r"(v.z), "r"(v.w) : "memory");
}
__device__ __forceinline__ void cpa16(uint32_t dst, const void* src) {
    asm volatile("cp.async.cg.shared.global [%0], [%1], 16;" :: "r"(dst), "l"(src));
}
__device__ __forceinline__ void ldsm4(uint32_t addr, uint32_t* r) {
    asm volatile("ldmatrix.sync.aligned.m8n8.x4.shared.b16 {%0,%1,%2,%3}, [%4];"
                 : "=r"(r[0]), "=r"(r[1]), "=r"(r[2]), "=r"(r[3]) : "r"(addr));
}
__device__ __forceinline__ void mma16816(float* d, const uint32_t* a, uint32_t b0, uint32_t b1) {
    asm volatile(
        "mma.sync.aligned.m16n8k16.row.col.f32.bf16.bf16.f32 "
        "{%0,%1,%2,%3},{%4,%5,%6,%7},{%8,%9},{%0,%1,%2,%3};"
        : "+f"(d[0]), "+f"(d[1]), "+f"(d[2]), "+f"(d[3])
        : "r"(a[0]), "r"(a[1]), "r"(a[2]), "r"(a[3]), "r"(b0), "r"(b1));
}
__device__ __forceinline__ void split2(float x, float y, uint32_t& hi, uint32_t& lo) {
    __nv_bfloat162 hb = __floats2bfloat162_rn(x, y);
    float2 hf = __bfloat1622float2(hb);
    __nv_bfloat162 lb = __floats2bfloat162_rn(x - hf.x, y - hf.y);
    hi = *(uint32_t*)&hb;
    lo = *(uint32_t*)&lb;
}

// 3-sweep inner compute
template <int ALO, int BHI, int BLO>
__device__ __forceinline__ void comp_chunk(
    uint32_t base, uint32_t aAddrBase, uint32_t bAddrBase, float (*acc)[8][4])
{
#pragma unroll
    for (int s = 0; s < 2; s++) {
        uint32_t ah[2][4], al2[2][4], bfr[4][4];
#pragma unroll
        for (int mt = 0; mt < 2; mt++) {
            uint32_t ad = base + aAddrBase + mt * 1280 + s * 32;
            ldsm4(ad, ah[mt]);
            ldsm4(ad + ALO, al2[mt]);
        }
#pragma unroll
        for (int pr = 0; pr < 4; pr++)
            ldsm4(base + BHI + bAddrBase + pr * 1280 + s * 32, bfr[pr]);
#pragma unroll
        for (int pr = 0; pr < 4; pr++)
#pragma unroll
            for (int mt = 0; mt < 2; mt++) {
                mma16816(acc[mt][2 * pr], ah[mt], bfr[pr][0], bfr[pr][1]);
                mma16816(acc[mt][2 * pr + 1], ah[mt], bfr[pr][2], bfr[pr][3]);
            }
#pragma unroll
        for (int pr = 0; pr < 4; pr++)
#pragma unroll
            for (int mt = 0; mt < 2; mt++) {
                mma16816(acc[mt][2 * pr], al2[mt], bfr[pr][0], bfr[pr][1]);
                mma16816(acc[mt][2 * pr + 1], al2[mt], bfr[pr][2], bfr[pr][3]);
            }
#pragma unroll
        for (int pr = 0; pr < 4; pr++)
            ldsm4(base + BLO + bAddrBase + pr * 1280 + s * 32, bfr[pr]);
#pragma unroll
        for (int pr = 0; pr < 4; pr++)
#pragma unroll
            for (int mt = 0; mt < 2; mt++) {
                mma16816(acc[mt][2 * pr], ah[mt], bfr[pr][0], bfr[pr][1]);
                mma16816(acc[mt][2 * pr + 1], ah[mt], bfr[pr][2], bfr[pr][3]);
            }
    }
}

// ---------------- big-tile cp.async GEMM ----------------
// MODE 0: plain fp32 C. MODE 1: QKV batched (z = weight index), split-head.
// MODE 2: logits (causal + scale, z = head)
template <int MODE>
__global__ void __launch_bounds__(512, 1) cp_gemm(
    const __nv_bfloat16* __restrict__ Ah, const __nv_bfloat16* __restrict__ Al,
    const __nv_bfloat16* __restrict__ Bh, const __nv_bfloat16* __restrict__ Bl,
    float* __restrict__ C,
    int Kd, int lda, int ldb, int ldc,
    size_t az, size_t bz, size_t cz)
{
    const int m0 = blockIdx.y * 256, n0 = blockIdx.x * 128, z = blockIdx.z;
    if (MODE == 2 && n0 >= m0 + 256) return;
    extern __shared__ char smem[];
    const uint32_t sb = smem_u32(smem);
    const int tid = threadIdx.x, lane = tid & 31, warp = tid >> 5;
    const int arow = tid & 255, aseg = tid >> 8;
    const int brow = tid >> 2, bq = tid & 3;

    const __nv_bfloat16* Ahb = Ah + (size_t)z * az;
    const __nv_bfloat16* Alb = Al + (size_t)z * az;
    const __nv_bfloat16* Bhb = Bh + (size_t)z * bz;
    const __nv_bfloat16* Blb = Bl + (size_t)z * bz;
    const int nch = Kd >> 5;

    float acc[2][8][4];
#pragma unroll
    for (int a = 0; a < 2; a++)
#pragma unroll
        for (int b = 0; b < 8; b++)
#pragma unroll
            for (int e = 0; e < 4; e++) acc[a][b][e] = 0.f;

    auto issue = [&](int c, int stg) {
        const int k0 = c << 5;
        const uint32_t st = sb + stg * G_STAGE;
        const uint32_t da = st + arow * 80 + aseg * 32;
        const __nv_bfloat16* pa = Ahb + (size_t)(m0 + arow) * lda + k0 + aseg * 16;
        cpa16(da, pa);               cpa16(da + 16, pa + 8);
        const __nv_bfloat16* pl = Alb + (size_t)(m0 + arow) * lda + k0 + aseg * 16;
        cpa16(da + G_ALO, pl);       cpa16(da + G_ALO + 16, pl + 8);
        const uint32_t db = st + brow * 80 + bq * 16;
        cpa16(db + G_BHI, Bhb + (size_t)(n0 + brow) * ldb + k0 + bq * 8);
        cpa16(db + G_BLO, Blb + (size_t)(n0 + brow) * ldb + k0 + bq * 8);
        asm volatile("cp.async.commit_group;");
    };

    const int warpM = (warp >> 1) * 32, warpN = (warp & 1) * 64;
    const uint32_t aAddrBase = (warpM + (lane & 15)) * 80 + (lane >> 4) * 16;
    const uint32_t bAddrBase = (warpN + ((lane >> 4) << 3) + (lane & 7)) * 80 + ((lane >> 3) & 1) * 16;

    issue(0, 0);
    if (nch > 1) issue(1, 1);
    int st = 0;
    for (int c = 0; c < nch; c++) {
        if (c + 1 < nch) asm volatile("cp.async.wait_group 1;");
        else             asm volatile("cp.async.wait_group 0;");
        __syncthreads();
        if (c + 2 < nch) {
            int stn = st + 2; if (stn >= 3) stn -= 3;
            issue(c + 2, stn);
        }
        comp_chunk<G_ALO, G_BHI, G_BLO>(sb + st * G_STAGE, aAddrBase, bAddrBase, acc);
        if (++st == 3) st = 0;
    }

    const int erow = lane >> 2, ecol = (lane & 3) * 2;
#pragma unroll
    for (int mt = 0; mt < 2; mt++) {
        int r0 = m0 + warpM + mt * 16 + erow;
        int r1 = r0 + 8;
#pragma unroll
        for (int nt = 0; nt < 8; nt++) {
            int c0 = n0 + warpN + nt * 8 + ecol;
            float d0 = acc[mt][nt][0], d1 = acc[mt][nt][1];
            float d2 = acc[mt][nt][2], d3 = acc[mt][nt][3];
            if (MODE == 0) {
                *(float2*)&C[(size_t)r0 * ldc + c0] = make_float2(d0, d1);
                *(float2*)&C[(size_t)r1 * ldc + c0] = make_float2(d2, d3);
            } else if (MODE == 1) {
                float* Cb = C + (size_t)z * cz;
                int hd = c0 >> 7, cl = c0 & 127;
                *(float2*)&Cb[((size_t)hd * S + r0) * HD + cl] = make_float2(d0, d1);
                *(float2*)&Cb[((size_t)hd * S + r1) * HD + cl] = make_float2(d2, d3);
            } else {
                const float iv = 1.f / SQRT_HD_F;
                float* Cb = C + (size_t)z * cz;
                float v0 = (c0 <= r0) ? d0 * iv : NEG_MIN_F;
                float v1 = (c0 + 1 <= r0) ? d1 * iv : NEG_MIN_F;
                float v2 = (c0 <= r1) ? d2 * iv : NEG_MIN_F;
                float v3 = (c0 + 1 <= r1) ? d3 * iv : NEG_MIN_F;
                *(float2*)&Cb[(size_t)r0 * ldc + c0] = make_float2(v0, v1);
                *(float2*)&Cb[(size_t)r1 * ldc + c0] = make_float2(v2, v3);
            }
        }
    }
}

// ---------------- PV GEMM (register A-path, evict mask only, heavy-first) ----------------
__global__ void __launch_bounds__(256, 1) pv_gemm(
    const float* __restrict__ Af,
    const __nv_bfloat16* __restrict__ Bh, const __nv_bfloat16* __restrict__ Bl,
    __nv_bfloat16* __restrict__ Coh, __nv_bfloat16* __restrict__ Col,
    int lda, int ldb,
    size_t az, size_t bz,
    const int* __restrict__ evBase, const float* __restrict__ rsBase)
{
    const int m0 = (15 - blockIdx.y) * 128, n0 = 0, z = blockIdx.z;
    extern __shared__ char smem[];
    const uint32_t sb = smem_u32(smem);
    const int tid = threadIdx.x, lane = tid & 31, warp = tid >> 5;
    const int arow = tid & 127, aseg = tid >> 7;

    const float* Afb = Af + (size_t)z * az;
    const int* evp = evBase + (size_t)z * S;
    const __nv_bfloat16* Bhb = Bh + (size_t)z * bz;
    const __nv_bfloat16* Blb = Bl + (size_t)z * bz;

    const int nch = (m0 + 128) >> 5;

    float acc[2][8][4];
#pragma unroll
    for (int a = 0; a < 2; a++)
#pragma unroll
        for (int b = 0; b < 8; b++)
#pragma unroll
            for (int e = 0; e < 4; e++) acc[a][b][e] = 0.f;

    uint4 rah[2], ral[2], rbh[2], rbl[2];

    auto ldg = [&](int k0) {
        const int kb = k0 + aseg * 16;
        const float* p = Afb + (size_t)(m0 + arow) * lda + kb;
        float f[16];
#pragma unroll
        for (int q = 0; q < 4; q++) *(float4*)&f[q * 4] = *(const float4*)(p + q * 4);
        const int r = m0 + arow;
        const int4* e4 = (const int4*)(evp + kb);
#pragma unroll
        for (int q = 0; q < 4; q++) {
            int4 e = e4[q];
            if (e.x < r) f[q * 4 + 0] = 0.f;
            if (e.y < r) f[q * 4 + 1] = 0.f;
            if (e.z < r) f[q * 4 + 2] = 0.f;
            if (e.w < r) f[q * 4 + 3] = 0.f;
        }
        uint32_t h[8], l[8];
#pragma unroll
        for (int q = 0; q < 8; q++) split2(f[q * 2], f[q * 2 + 1], h[q], l[q]);
        rah[0] = make_uint4(h[0], h[1], h[2], h[3]); rah[1] = make_uint4(h[4], h[5], h[6], h[7]);
        ral[0] = make_uint4(l[0], l[1], l[2], l[3]); ral[1] = make_uint4(l[4], l[5], l[6], l[7]);
        const uint4* qh = (const uint4*)(Bhb + (size_t)(n0 + arow) * ldb + kb);
        rbh[0] = qh[0]; rbh[1] = qh[1];
        const uint4* ql = (const uint4*)(Blb + (size_t)(n0 + arow) * ldb + kb);
        rbl[0] = ql[0]; rbl[1] = ql[1];
    };
    auto sts = [&](int buf) {
        uint32_t b = sb + buf * 40960 + arow * 80 + aseg * 32;
        sts128(b, rah[0]);          sts128(b + 16, rah[1]);
        sts128(b + 10240, ral[0]);  sts128(b + 10240 + 16, ral[1]);
        sts128(b + 20480, rbh[0]);  sts128(b + 20480 + 16, rbh[1]);
        sts128(b + 30720, rbl[0]);  sts128(b + 30720 + 16, rbl[1]);
    };

    const int warpM = (warp >> 1) * 32, warpN = (warp & 1) * 64;
    const uint32_t aAddrBase = (warpM + (lane & 15)) * 80 + (lane >> 4) * 16;
    const uint32_t bAddrBase = (warpN + ((lane >> 4) << 3) + (lane & 7)) * 80 + ((lane >> 3) & 1) * 16;

    ldg(0);
    sts(0);
    __syncthreads();
    for (int c = 0; c < nch; c++) {
        if (c + 1 < nch) ldg((c + 1) << 5);
        comp_chunk<10240, 20480, 30720>(sb + (c & 1) * 40960, aAddrBase, bAddrBase, acc);
        if (c + 1 < nch) sts((c + 1) & 1);
        __syncthreads();
    }

    const int erow = lane >> 2, ecol = (lane & 3) * 2;
#pragma unroll
    for (int mt = 0; mt < 2; mt++) {
        int r0 = m0 + warpM + mt * 16 + erow;
        int r1 = r0 + 8;
        float inv0 = 1.f / rsBase[(size_t)z * S + r0];
        float inv1 = 1.f / rsBase[(size_t)z * S + r1];
#pragma unroll
        for (int nt = 0; nt < 8; nt++) {
            int c0 = n0 + warpN + nt * 8 + ecol;
            float v0 = acc[mt][nt][0] * inv0, v1 = acc[mt][nt][1] * inv0;
            float v2 = acc[mt][nt][2] * inv1, v3 = acc[mt][nt][3] * inv1;
            uint32_t h0, l0, h1, l1;
            split2(v0, v1, h0, l0);
            split2(v2, v3, h1, l1);
            size_t o0 = (size_t)r0 * Dm + z * HD + c0;
            size_t o1 = (size_t)r1 * Dm + z * HD + c0;
            *(uint32_t*)&Coh[o0] = h0; *(uint32_t*)&Col[o0] = l0;
            *(uint32_t*)&Coh[o1] = h1; *(uint32_t*)&Col[o1] = l1;
        }
    }
}

// ---------------- fp32 -> bf16 hi/lo split (single) ----------------
__global__ void __launch_bounds__(256) split_kernel(
    const float* __restrict__ x, __nv_bfloat16* __restrict__ hi, __nv_bfloat16* __restrict__ lo)
{
    int i = (blockIdx.x * 256 + threadIdx.x) * 8;
    float f[8];
    *(float4*)&f[0] = *(const float4*)(x + i);
    *(float4*)&f[4] = *(const float4*)(x + i + 4);
    uint32_t h[4], l[4];
#pragma unroll
    for (int q = 0; q < 4; q++) split2(f[q * 2], f[q * 2 + 1], h[q], l[q]);
    *(uint4*)(hi + i) = make_uint4(h[0], h[1], h[2], h[3]);
    *(uint4*)(lo + i) = make_uint4(l[0], l[1], l[2], l[3]);
}

// ---------------- batched weight split (wq/wk/wv by z) ----------------
__global__ void __launch_bounds__(256) split3_kernel(
    const float* __restrict__ w0, const float* __restrict__ w1, const float* __restrict__ w2,
    __nv_bfloat16* __restrict__ base)
{
    const int z = blockIdx.z;
    const float* x = (z == 0) ? w0 : (z == 1) ? w1 : w2;
    __nv_bfloat16* hi = base + (size_t)z * 2 * Dm * Dm;
    __nv_bfloat16* lo = hi + (size_t)Dm * Dm;
    int i = (blockIdx.x * 256 + threadIdx.x) * 8;
    float f[8];
    *(float4*)&f[0] = *(const float4*)(x + i);
    *(float4*)&f[4] = *(const float4*)(x + i + 4);
    uint32_t h[4], l[4];
#pragma unroll
    for (int q = 0; q < 4; q++) split2(f[q * 2], f[q * 2 + 1], h[q], l[q]);
    *(uint4*)(hi + i) = make_uint4(h[0], h[1], h[2], h[3]);
    *(uint4*)(lo + i) = make_uint4(l[0], l[1], l[2], l[3]);
}

// ---------------- RoPE (fp32 in -> bf16 split out) ----------------
__global__ void __launch_bounds__(64) rope_split_kernel(const int* __restrict__ pos_ids)
{
    int hs = blockIdx.x;
    int h = hs / S, s = hs % S;
    int d = threadIdx.x;
    float posf = (float)pos_ids[s];
    float invf = powf(10000.f, -((float)d) / 64.f);
    float fr = posf * invf;
    float c = cosf(fr), sn = sinf(fr);
    size_t base = ((size_t)h * S + s) * HD;
    const float* Q = g_QKV;
    const float* K = g_QKV + (size_t)Hh * S * HD;
    float q1 = Q[base + d], q2 = Q[base + d + 64];
    float k1 = K[base + d], k2 = K[base + d + 64];
    float qa = q1 * c - q2 * sn, qb = q2 * c + q1 * sn;
    float ka = k1 * c - k2 * sn, kb = k2 * c + k1 * sn;
#define WR(arr_h, arr_l, off, v) do { \
        __nv_bfloat16 _hb = __float2bfloat16_rn(v); \
        arr_h[base + (off)] = _hb; \
        arr_l[base + (off)] = __float2bfloat16_rn((v) - __bfloat162float(_hb)); } while (0)
    WR(g_Qbh, g_Qbl, d, qa);
    WR(g_Qbh, g_Qbl, d + 64, qb);
    WR(g_Kbh, g_Kbl, d, ka);
    WR(g_Kbh, g_Kbl, d + 64, kb);
#undef WR
}

// ---------------- V transpose + split ----------------
__global__ void __launch_bounds__(256) vtrans_kernel()
{
    __shared__ float tile[32][33];
    int h = blockIdx.z, s0 = blockIdx.x * 32, d0 = blockIdx.y * 32;
    int tx = threadIdx.x & 31, ty = threadIdx.x >> 5;
    const float* Vb = g_QKV + (size_t)2 * Hh * S * HD + (size_t)h * S * HD;
#pragma unroll
    for (int i = 0; i < 4; i++)
        tile[ty * 4 + i][tx] = Vb[(size_t)(s0 + ty * 4 + i) * HD + d0 + tx];
    __syncthreads();
#pragma unroll
    for (int i = 0; i < 4; i++) {
        int d = d0 + ty * 4 + i;
        float v = tile[tx][ty * 4 + i];
        __nv_bfloat16 hb = __float2bfloat16_rn(v);
        g_VTh[((size_t)h * HD + d) * S + s0 + tx] = hb;
        g_VTl[((size_t)h * HD + d) * S + s0 + tx] = __float2bfloat16_rn(v - __bfloat162float(hb));
    }
}

// ---------------- softmax: triangular reads, exp-skip branches, full zero writes ----------------
__global__ void __launch_bounds__(256) softmax_kernel()
{
    int r = blockIdx.x, h = blockIdx.y, tid = threadIdx.x;
    float* row = g_scores + ((size_t)h * S + r) * S;
    float4* row4 = (float4*)row;
    const int n = r + 1;
    const int nv = (r >> 2) + 1;     // float4s containing any valid data
    __shared__ float sred[9];

    float4 v0 = make_float4(NEG_MIN_F, NEG_MIN_F, NEG_MIN_F, NEG_MIN_F), v1 = v0;
    if (tid < nv) v0 = row4[tid];
    if (tid + 256 < nv) v1 = row4[tid + 256];
    const int p0 = tid * 4, p1 = 1024 + tid * 4;
    float mx = NEG_MIN_F;
    if (p0 < n) {
        mx = fmaxf(mx, v0.x);
        mx = fmaxf(mx, (p0 + 1 < n) ? v0.y : NEG_MIN_F);
        mx = fmaxf(mx, (p0 + 2 < n) ? v0.z : NEG_MIN_F);
        mx = fmaxf(mx, (p0 + 3 < n) ? v0.w : NEG_MIN_F);
    }
    if (p1 < n) {
        mx = fmaxf(mx, v1.x);
        mx = fmaxf(mx, (p1 + 1 < n) ? v1.y : NEG_MIN_F);
        mx = fmaxf(mx, (p1 + 2 < n) ? v1.z : NEG_MIN_F);
        mx = fmaxf(mx, (p1 + 3 < n) ? v1.w : NEG_MIN_F);
    }
#pragma unroll
    for (int o = 16; o > 0; o >>= 1) mx = fmaxf(mx, __shfl_xor_sync(0xffffffffu, mx, o));
    if ((tid & 31) == 0) sred[tid >> 5] = mx;
    __syncthreads();
    if (tid == 0) { float m = sred[0]; for (int i = 1; i < 8; i++) m = fmaxf(m, sred[i]); sred[8] = m; }
    __syncthreads();
    mx = sred[8];
    __syncthreads();

    float4 e0 = make_float4(0.f, 0.f, 0.f, 0.f), e1 = e0;
    float loc = 0.f;
    if (p0 < n) {
        e0.x = __expf(v0.x - mx);
        e0.y = (p0 + 1 < n) ? __expf(v0.y - mx) : 0.f;
        e0.z = (p0 + 2 < n) ? __expf(v0.z - mx) : 0.f;
        e0.w = (p0 + 3 < n) ? __expf(v0.w - mx) : 0.f;
        loc += e0.x + e0.y + e0.z + e0.w;
    }
    if (p1 < n) {
        e1.x = __expf(v1.x - mx);
        e1.y = (p1 + 1 < n) ? __expf(v1.y - mx) : 0.f;
        e1.z = (p1 + 2 < n) ? __expf(v1.z - mx) : 0.f;
        e1.w = (p1 + 3 < n) ? __expf(v1.w - mx) : 0.f;
        loc += e1.x + e1.y + e1.z + e1.w;
    }
#pragma unroll
    for (int o = 16; o > 0; o >>= 1) loc += __shfl_xor_sync(0xffffffffu, loc, o);
    if ((tid & 31) == 0) sred[tid >> 5] = loc;
    __syncthreads();
    if (tid == 0) {
        float s2 = 0.f;
        for (int i = 0; i < 8; i++) s2 += sred[i];
        g_rownorm[h * S + r] = s2;
        g_rowsum[h * S + r] = s2;
    }

    row4[tid] = e0;
    row4[tid + 256] = e1;
}

// ---------------- eviction scan: 4-deep pipeline, half-warp sum (4-shfl chain) ----------------
__global__ void __launch_bounds__(256) scan_kernel()
{
    const int h = blockIdx.x, tid = threadIdx.x;
    const int lane = tid & 31, warp = tid >> 5;
    const float* sc = g_scores + (size_t)h * S * S;
    __shared__ float coefEff[CACHE];
    __shared__ uint4 sRed[2][8];
    __shared__ float sSum2[2][8];
    __shared__ float sInit[8];

#pragma unroll
    for (int i = 0; i < 8; i++) g_evict[h * S + tid + i * 256] = 0x7fffffff;

    for (int i = tid; i < CACHE; i += 256)
        coefEff[i] = powf(PENALTY, (float)(CACHE - 1 - i)) / g_rownorm[h * S + i];
    __syncthreads();

    float sel[8];
#pragma unroll
    for (int i = 0; i < 8; i++) sel[i] = 0.f;

    for (int rrow = WARM_START; rrow < CACHE; rrow++) {
        float cf = coefEff[rrow];
        if (cf != 0.f) {
            const float* rp = sc + (size_t)rrow * S + tid;
            sel[0] = fmaf(cf, rp[0],   sel[0]);
            sel[1] = fmaf(cf, rp[256], sel[1]);
        }
    }

    // 4-deep register row pipeline: r = row t, n1 = t+1, n2 = t+2, n3 = t+3
    float r[8], n1[8], n2[8], n3[8];
    {
        const float* rp = sc + (size_t)CACHE * S + tid;
#pragma unroll
        for (int i = 0; i < 8; i++) r[i] = rp[i * 256];
        const float* q1 = sc + (size_t)(CACHE + 1) * S + tid;
#pragma unroll
        for (int i = 0; i < 8; i++) n1[i] = q1[i * 256];
        const float* q2 = sc + (size_t)(CACHE + 2) * S + tid;
#pragma unroll
        for (int i = 0; i < 8; i++) n2[i] = q2[i * 256];
        const float* q3 = sc + (size_t)(CACHE + 3) * S + tid;
#pragma unroll
        for (int i = 0; i < 8; i++) n3[i] = q3[i * 256];
    }
    float tot;
    {
        float loc = 0.f;
#pragma unroll
        for (int i = 0; i < 8; i++) loc += r[i];
#pragma unroll
        for (int o = 16; o > 0; o >>= 1) loc += __shfl_xor_sync(0xffffffffu, loc, o);
        if (lane == 0) sInit[warp] = loc;
        __syncthreads();
        float s2 = 0.f;
#pragma unroll
        for (int w = 0; w < 8; w++) s2 += sInit[w];
        tot = s2;
    }

    for (int t = CACHE; t < S - 1; t++) {
        const int buf = t & 1;
        const int lim = t - RECENT;
        const float inv = 1.0f / tot;
        unsigned long long key = ~0ull;
        float pay = 0.f, sg = 0.f;
#pragma unroll
        for (int i = 0; i < 8; i++) {
            bool keep = (sel[i] <= 1.0e30f);
            float c = keep ? r[i] : 0.f;
            float ns = __fadd_rn(__fmul_rn(PENALTY, sel[i]), __fmul_rn(c, inv));
            sel[i] = ns;
            sg += keep ? n1[i] : 0.f;
            int p = tid + (i << 8);
            if (p <= lim) {
                unsigned long long k2 =
                    ((unsigned long long)__float_as_uint(ns) << 32) | (unsigned)p;
                if (k2 < key) { key = k2; pay = n1[i]; }
            }
        }
        // shift + issue next row loads EARLY (before reductions)
#pragma unroll
        for (int i = 0; i < 8; i++) { r[i] = n1[i]; n1[i] = n2[i]; n2[i] = n3[i]; }
        if (t + 4 < S) {
            const float* rp = sc + (size_t)(t + 4) * S + tid;
#pragma unroll
            for (int i = 0; i < 8; i++) n3[i] = rp[i * 256];
        }

        // half-warp sum: 4 shfl steps (offsets 8,4,2,1) -> lanes 0-15 hold half0, 16-31 half1
        float wsum = sg;
#pragma unroll
        for (int o = 8; o > 0; o >>= 1) wsum += __shfl_xor_sync(0xffffffffu, wsum, o);
        uint32_t lv = (uint32_t)(key >> 32), lp = (uint32_t)key;
        uint32_t vmin = __reduce_min_sync(0xffffffffu, lv);
        uint32_t pmin = __reduce_min_sync(0xffffffffu, (lv == vmin) ? lp : 0xffffffffu);
        float wpay = __shfl_sync(0xffffffffu, pay, (int)(pmin & 31));
        if (lane == 0)
            sRed[buf][warp] = make_uint4(vmin, pmin, __float_as_uint(wsum), __float_as_uint(wpay));
        if (lane == 16) sSum2[buf][warp] = wsum;
        __syncthreads();
        uint4 q0 = sRed[buf][0];
        unsigned long long gk = ((unsigned long long)q0.x << 32) | q0.y;
        float gs = __uint_as_float(q0.z) + sSum2[buf][0];
        float gpay = __uint_as_float(q0.w);
#pragma unroll
        for (int w = 1; w < 8; w++) {
            uint4 q = sRed[buf][w];
            unsigned long long kk = ((unsigned long long)q.x << 32) | q.y;
            gs += __uint_as_float(q.z) + sSum2[buf][w];
            if (kk < gk) { gk = kk; gpay = __uint_as_float(q.w); }
        }
        int mpos = (int)(gk & 0xffffffffu);
        tot = gs - gpay;

        if (tid == 0) g_rowsum[h * S + t + 1] = tot;
        if ((mpos & 255) == tid) {
            sel[mpos >> 8] = __int_as_float(0x7f800000);
            g_evict[h * S + mpos] = t;
        }
    }
}

// ---------------- launch ----------------
extern "C" void kernel_launch(void* const* d_in, const int* in_sizes, int n_in,
                              void* d_out, int out_size)
{
    (void)in_sizes; (void)n_in; (void)out_size;
    const float* hs  = (const float*)d_in[0];
    const int*   pos = (const int*)d_in[2];
    const float* wq  = (const float*)d_in[3];
    const float* wk  = (const float*)d_in[4];
    const float* wv  = (const float*)d_in[5];
    const float* wo  = (const float*)d_in[6];
    float* out = (float*)d_out;

    float *pQKV, *pS, *pRs;
    int* pEv;
    __nv_bfloat16 *pHSh, *pHSl, *pW, *pQh, *pQl, *pKh, *pKl, *pVTh, *pVTl, *pAOh, *pAOl;
    cudaGetSymbolAddress((void**)&pQKV, g_QKV);
    cudaGetSymbolAddress((void**)&pS,   g_scores);
    cudaGetSymbolAddress((void**)&pRs,  g_rowsum);
    cudaGetSymbolAddress((void**)&pEv,  g_evict);
    cudaGetSymbolAddress((void**)&pHSh, g_HSh);
    cudaGetSymbolAddress((void**)&pHSl, g_HSl);
    cudaGetSymbolAddress((void**)&pW,   g_Wsp);
    cudaGetSymbolAddress((void**)&pQh,  g_Qbh);
    cudaGetSymbolAddress((void**)&pQl,  g_Qbl);
    cudaGetSymbolAddress((void**)&pKh,  g_Kbh);
    cudaGetSymbolAddress((void**)&pKl,  g_Kbl);
    cudaGetSymbolAddress((void**)&pVTh, g_VTh);
    cudaGetSymbolAddress((void**)&pVTl, g_VTl);
    cudaGetSymbolAddress((void**)&pAOh, g_AOh);
    cudaGetSymbolAddress((void**)&pAOl, g_AOl);

    const size_t DD = (size_t)Dm * Dm;
    __nv_bfloat16* woh = pW + 6 * DD; __nv_bfloat16* wol = pW + 7 * DD;

    cudaFuncSetAttribute(cp_gemm<0>, cudaFuncAttributeMaxDynamicSharedMemorySize, G_SMEM);
    cudaFuncSetAttribute(cp_gemm<1>, cudaFuncAttributeMaxDynamicSharedMemorySize, G_SMEM);
    cudaFuncSetAttribute(cp_gemm<2>, cudaFuncAttributeMaxDynamicSharedMemorySize, G_SMEM);
    cudaFuncSetAttribute(pv_gemm,    cudaFuncAttributeMaxDynamicSharedMemorySize, PV_SMEM);

    const int splitGrid = (int)(DD / (256 * 8));
    split_kernel<<<splitGrid, 256>>>(hs, pHSh, pHSl);
    split3_kernel<<<dim3(splitGrid, 1, 3), 256>>>(wq, wk, wv, pW);
    split_kernel<<<splitGrid, 256>>>(wo, woh, wol);
    // slot 4 (profiled): merged QKV projection
    cp_gemm<1><<<dim3(16, 8, 3), 512, G_SMEM>>>(pHSh, pHSl, pW, pW + DD, pQKV,
        Dm, Dm, Dm, Dm, 0, 2 * DD, (size_t)Hh * S * HD);
    rope_split_kernel<<<Hh * S, 64>>>(pos);
    vtrans_kernel<<<dim3(S / 32, HD / 32, Hh), 256>>>();
    cp_gemm<2><<<dim3(16, 8, Hh), 512, G_SMEM>>>(pQh, pQl, pKh, pKl, pS,
        HD, HD, HD, S, (size_t)S * HD, (size_t)S * HD, (size_t)S * S);
    softmax_kernel<<<dim3(S, Hh), 256>>>();
    scan_kernel<<<Hh, 256>>>();
    pv_gemm<<<dim3(1, 16, Hh), 256, PV_SMEM>>>(pS, pVTh, pVTl, pAOh, pAOl,
        S, S, (size_t)S * S, (size_t)HD * S, pEv, pRs);
    cp_gemm<0><<<dim3(16, 8, 1), 512, G_SMEM>>>(pAOh, pAOl, woh, wol, out,
        Dm, Dm, Dm, Dm, 0, 0, 0);
}

// round 17
// speedup vs baseline: 1.1578x; 1.0724x over previous
#include <cuda_runtime.h>
#include <cuda_bf16.h>
#include <cstdint>
#include <cstdio>

#define S 2048
#define Dm 2048
#define Hh 16
#define HD 128
#define CACHE 408
#define RECENT 204
#define PENALTY 0.4f
#define NEG_MIN_F (-3.4028234663852886e38f)
#define SQRT_HD_F 11.313708498984761f
#define WARM_START 288

#define G_ALO 20480
#define G_BHI 40960
#define G_BLO 51200
#define G_STAGE 61440
#define G_SMEM (3 * G_STAGE)
#define PV_SMEM 81920

// ---------------- scratch ----------------
__device__ float g_QKV[3 * Hh * S * HD];      // Q | K | V
__device__ float g_scores[Hh * S * S];
__device__ float g_rownorm[Hh * S];
__device__ float g_rowsum[Hh * S];
__device__ int   g_evict[Hh * S];
__device__ __nv_bfloat16 g_HSh[Dm * Dm], g_HSl[Dm * Dm];
__device__ __nv_bfloat16 g_Wsp[8 * Dm * Dm];  // wqh,wql,wkh,wkl,wvh,wvl,woh,wol
__device__ __nv_bfloat16 g_Qbh[Hh * S * HD], g_Qbl[Hh * S * HD];
__device__ __nv_bfloat16 g_Kbh[Hh * S * HD], g_Kbl[Hh * S * HD];
__device__ __nv_bfloat16 g_VTh[Hh * HD * S], g_VTl[Hh * HD * S];
__device__ __nv_bfloat16 g_AOh[S * Dm], g_AOl[S * Dm];

// ---------------- helpers ----------------
__device__ __forceinline__ uint32_t smem_u32(const void* p) {
    uint32_t a;
    asm("{ .reg .u64 t; cvta.to.shared.u64 t, %1; cvt.u32.u64 %0, t; }" : "=r"(a) : "l"(p));
    return a;
}
__device__ __forceinline__ void sts128(uint32_t addr, uint4 v) {
    asm volatile("st.shared.v4.b32 [%0], {%1,%2,%3,%4};"
                 :: "r"(addr), "r"(v.x), "r"(v.y), "r"(v.z), "r"(v.w) : "memory");
}
__device__ __forceinline__ void cpa16(uint32_t dst, const void* src) {
    asm volatile("cp.async.cg.shared.global [%0], [%1], 16;" :: "r"(dst), "l"(src));
}
__device__ __forceinline__ void ldsm4(uint32_t addr, uint32_t* r) {
    asm volatile("ldmatrix.sync.aligned.m8n8.x4.shared.b16 {%0,%1,%2,%3}, [%4];"
                 : "=r"(r[0]), "=r"(r[1]), "=r"(r[2]), "=r"(r[3]) : "r"(addr));
}
__device__ __forceinline__ void mma16816(float* d, const uint32_t* a, uint32_t b0, uint32_t b1) {
    asm volatile(
        "mma.sync.aligned.m16n8k16.row.col.f32.bf16.bf16.f32 "
        "{%0,%1,%2,%3},{%4,%5,%6,%7},{%8,%9},{%0,%1,%2,%3};"
        : "+f"(d[0]), "+f"(d[1]), "+f"(d[2]), "+f"(d[3])
        : "r"(a[0]), "r"(a[1]), "r"(a[2]), "r"(a[3]), "r"(b0), "r"(b1));
}
__device__ __forceinline__ void split2(float x, float y, uint32_t& hi, uint32_t& lo) {
    __nv_bfloat162 hb = __floats2bfloat162_rn(x, y);
    float2 hf = __bfloat1622float2(hb);
    __nv_bfloat162 lb = __floats2bfloat162_rn(x - hf.x, y - hf.y);
    hi = *(uint32_t*)&hb;
    lo = *(uint32_t*)&lb;
}

// 3-sweep inner compute
template <int ALO, int BHI, int BLO>
__device__ __forceinline__ void comp_chunk(
    uint32_t base, uint32_t aAddrBase, uint32_t bAddrBase, float (*acc)[8][4])
{
#pragma unroll
    for (int s = 0; s < 2; s++) {
        uint32_t ah[2][4], al2[2][4], bfr[4][4];
#pragma unroll
        for (int mt = 0; mt < 2; mt++) {
            uint32_t ad = base + aAddrBase + mt * 1280 + s * 32;
            ldsm4(ad, ah[mt]);
            ldsm4(ad + ALO, al2[mt]);
        }
#pragma unroll
        for (int pr = 0; pr < 4; pr++)
            ldsm4(base + BHI + bAddrBase + pr * 1280 + s * 32, bfr[pr]);
#pragma unroll
        for (int pr = 0; pr < 4; pr++)
#pragma unroll
            for (int mt = 0; mt < 2; mt++) {
                mma16816(acc[mt][2 * pr], ah[mt], bfr[pr][0], bfr[pr][1]);
                mma16816(acc[mt][2 * pr + 1], ah[mt], bfr[pr][2], bfr[pr][3]);
            }
#pragma unroll
        for (int pr = 0; pr < 4; pr++)
#pragma unroll
            for (int mt = 0; mt < 2; mt++) {
                mma16816(acc[mt][2 * pr], al2[mt], bfr[pr][0], bfr[pr][1]);
                mma16816(acc[mt][2 * pr + 1], al2[mt], bfr[pr][2], bfr[pr][3]);
            }
#pragma unroll
        for (int pr = 0; pr < 4; pr++)
            ldsm4(base + BLO + bAddrBase + pr * 1280 + s * 32, bfr[pr]);
#pragma unroll
        for (int pr = 0; pr < 4; pr++)
#pragma unroll
            for (int mt = 0; mt < 2; mt++) {
                mma16816(acc[mt][2 * pr], ah[mt], bfr[pr][0], bfr[pr][1]);
                mma16816(acc[mt][2 * pr + 1], ah[mt], bfr[pr][2], bfr[pr][3]);
            }
    }
}

// ---------------- big-tile cp.async GEMM ----------------
// MODE 0: plain fp32 C. MODE 1: QKV batched (z = weight index), split-head.
// MODE 2: logits (causal + scale, z = head)
template <int MODE>
__global__ void __launch_bounds__(512, 1) cp_gemm(
    const __nv_bfloat16* __restrict__ Ah, const __nv_bfloat16* __restrict__ Al,
    const __nv_bfloat16* __restrict__ Bh, const __nv_bfloat16* __restrict__ Bl,
    float* __restrict__ C,
    int Kd, int lda, int ldb, int ldc,
    size_t az, size_t bz, size_t cz)
{
    const int m0 = blockIdx.y * 256, n0 = blockIdx.x * 128, z = blockIdx.z;
    if (MODE == 2 && n0 >= m0 + 256) return;
    extern __shared__ char smem[];
    const uint32_t sb = smem_u32(smem);
    const int tid = threadIdx.x, lane = tid & 31, warp = tid >> 5;
    const int arow = tid & 255, aseg = tid >> 8;
    const int brow = tid >> 2, bq = tid & 3;

    const __nv_bfloat16* Ahb = Ah + (size_t)z * az;
    const __nv_bfloat16* Alb = Al + (size_t)z * az;
    const __nv_bfloat16* Bhb = Bh + (size_t)z * bz;
    const __nv_bfloat16* Blb = Bl + (size_t)z * bz;
    const int nch = Kd >> 5;

    float acc[2][8][4];
#pragma unroll
    for (int a = 0; a < 2; a++)
#pragma unroll
        for (int b = 0; b < 8; b++)
#pragma unroll
            for (int e = 0; e < 4; e++) acc[a][b][e] = 0.f;

    auto issue = [&](int c, int stg) {
        const int k0 = c << 5;
        const uint32_t st = sb + stg * G_STAGE;
        const uint32_t da = st + arow * 80 + aseg * 32;
        const __nv_bfloat16* pa = Ahb + (size_t)(m0 + arow) * lda + k0 + aseg * 16;
        cpa16(da, pa);               cpa16(da + 16, pa + 8);
        const __nv_bfloat16* pl = Alb + (size_t)(m0 + arow) * lda + k0 + aseg * 16;
        cpa16(da + G_ALO, pl);       cpa16(da + G_ALO + 16, pl + 8);
        const uint32_t db = st + brow * 80 + bq * 16;
        cpa16(db + G_BHI, Bhb + (size_t)(n0 + brow) * ldb + k0 + bq * 8);
        cpa16(db + G_BLO, Blb + (size_t)(n0 + brow) * ldb + k0 + bq * 8);
        asm volatile("cp.async.commit_group;");
    };

    const int warpM = (warp >> 1) * 32, warpN = (warp & 1) * 64;
    const uint32_t aAddrBase = (warpM + (lane & 15)) * 80 + (lane >> 4) * 16;
    const uint32_t bAddrBase = (warpN + ((lane >> 4) << 3) + (lane & 7)) * 80 + ((lane >> 3) & 1) * 16;

    issue(0, 0);
    if (nch > 1) issue(1, 1);
    int st = 0;
    for (int c = 0; c < nch; c++) {
        if (c + 1 < nch) asm volatile("cp.async.wait_group 1;");
        else             asm volatile("cp.async.wait_group 0;");
        __syncthreads();
        if (c + 2 < nch) {
            int stn = st + 2; if (stn >= 3) stn -= 3;
            issue(c + 2, stn);
        }
        comp_chunk<G_ALO, G_BHI, G_BLO>(sb + st * G_STAGE, aAddrBase, bAddrBase, acc);
        if (++st == 3) st = 0;
    }

    const int erow = lane >> 2, ecol = (lane & 3) * 2;
#pragma unroll
    for (int mt = 0; mt < 2; mt++) {
        int r0 = m0 + warpM + mt * 16 + erow;
        int r1 = r0 + 8;
#pragma unroll
        for (int nt = 0; nt < 8; nt++) {
            int c0 = n0 + warpN + nt * 8 + ecol;
            float d0 = acc[mt][nt][0], d1 = acc[mt][nt][1];
            float d2 = acc[mt][nt][2], d3 = acc[mt][nt][3];
            if (MODE == 0) {
                *(float2*)&C[(size_t)r0 * ldc + c0] = make_float2(d0, d1);
                *(float2*)&C[(size_t)r1 * ldc + c0] = make_float2(d2, d3);
            } else if (MODE == 1) {
                float* Cb = C + (size_t)z * cz;
                int hd = c0 >> 7, cl = c0 & 127;
                *(float2*)&Cb[((size_t)hd * S + r0) * HD + cl] = make_float2(d0, d1);
                *(float2*)&Cb[((size_t)hd * S + r1) * HD + cl] = make_float2(d2, d3);
            } else {
                const float iv = 1.f / SQRT_HD_F;
                float* Cb = C + (size_t)z * cz;
                float v0 = (c0 <= r0) ? d0 * iv : NEG_MIN_F;
                float v1 = (c0 + 1 <= r0) ? d1 * iv : NEG_MIN_F;
                float v2 = (c0 <= r1) ? d2 * iv : NEG_MIN_F;
                float v3 = (c0 + 1 <= r1) ? d3 * iv : NEG_MIN_F;
                *(float2*)&Cb[(size_t)r0 * ldc + c0] = make_float2(v0, v1);
                *(float2*)&Cb[(size_t)r1 * ldc + c0] = make_float2(v2, v3);
            }
        }
    }
}

// ---------------- PV GEMM (register A-path, evict mask only, heavy-first) ----------------
__global__ void __launch_bounds__(256, 1) pv_gemm(
    const float* __restrict__ Af,
    const __nv_bfloat16* __restrict__ Bh, const __nv_bfloat16* __restrict__ Bl,
    __nv_bfloat16* __restrict__ Coh, __nv_bfloat16* __restrict__ Col,
    int lda, int ldb,
    size_t az, size_t bz,
    const int* __restrict__ evBase, const float* __restrict__ rsBase)
{
    const int m0 = (15 - blockIdx.y) * 128, n0 = 0, z = blockIdx.z;
    extern __shared__ char smem[];
    const uint32_t sb = smem_u32(smem);
    const int tid = threadIdx.x, lane = tid & 31, warp = tid >> 5;
    const int arow = tid & 127, aseg = tid >> 7;

    const float* Afb = Af + (size_t)z * az;
    const int* evp = evBase + (size_t)z * S;
    const __nv_bfloat16* Bhb = Bh + (size_t)z * bz;
    const __nv_bfloat16* Blb = Bl + (size_t)z * bz;

    const int nch = (m0 + 128) >> 5;

    float acc[2][8][4];
#pragma unroll
    for (int a = 0; a < 2; a++)
#pragma unroll
        for (int b = 0; b < 8; b++)
#pragma unroll
            for (int e = 0; e < 4; e++) acc[a][b][e] = 0.f;

    uint4 rah[2], ral[2], rbh[2], rbl[2];

    auto ldg = [&](int k0) {
        const int kb = k0 + aseg * 16;
        const float* p = Afb + (size_t)(m0 + arow) * lda + kb;
        float f[16];
#pragma unroll
        for (int q = 0; q < 4; q++) *(float4*)&f[q * 4] = *(const float4*)(p + q * 4);
        const int r = m0 + arow;
        const int4* e4 = (const int4*)(evp + kb);
#pragma unroll
        for (int q = 0; q < 4; q++) {
            int4 e = e4[q];
            if (e.x < r) f[q * 4 + 0] = 0.f;
            if (e.y < r) f[q * 4 + 1] = 0.f;
            if (e.z < r) f[q * 4 + 2] = 0.f;
            if (e.w < r) f[q * 4 + 3] = 0.f;
        }
        uint32_t h[8], l[8];
#pragma unroll
        for (int q = 0; q < 8; q++) split2(f[q * 2], f[q * 2 + 1], h[q], l[q]);
        rah[0] = make_uint4(h[0], h[1], h[2], h[3]); rah[1] = make_uint4(h[4], h[5], h[6], h[7]);
        ral[0] = make_uint4(l[0], l[1], l[2], l[3]); ral[1] = make_uint4(l[4], l[5], l[6], l[7]);
        const uint4* qh = (const uint4*)(Bhb + (size_t)(n0 + arow) * ldb + kb);
        rbh[0] = qh[0]; rbh[1] = qh[1];
        const uint4* ql = (const uint4*)(Blb + (size_t)(n0 + arow) * ldb + kb);
        rbl[0] = ql[0]; rbl[1] = ql[1];
    };
    auto sts = [&](int buf) {
        uint32_t b = sb + buf * 40960 + arow * 80 + aseg * 32;
        sts128(b, rah[0]);          sts128(b + 16, rah[1]);
        sts128(b + 10240, ral[0]);  sts128(b + 10240 + 16, ral[1]);
        sts128(b + 20480, rbh[0]);  sts128(b + 20480 + 16, rbh[1]);
        sts128(b + 30720, rbl[0]);  sts128(b + 30720 + 16, rbl[1]);
    };

    const int warpM = (warp >> 1) * 32, warpN = (warp & 1) * 64;
    const uint32_t aAddrBase = (warpM + (lane & 15)) * 80 + (lane >> 4) * 16;
    const uint32_t bAddrBase = (warpN + ((lane >> 4) << 3) + (lane & 7)) * 80 + ((lane >> 3) & 1) * 16;

    ldg(0);
    sts(0);
    __syncthreads();
    for (int c = 0; c < nch; c++) {
        if (c + 1 < nch) ldg((c + 1) << 5);
        comp_chunk<10240, 20480, 30720>(sb + (c & 1) * 40960, aAddrBase, bAddrBase, acc);
        if (c + 1 < nch) sts((c + 1) & 1);
        __syncthreads();
    }

    const int erow = lane >> 2, ecol = (lane & 3) * 2;
#pragma unroll
    for (int mt = 0; mt < 2; mt++) {
        int r0 = m0 + warpM + mt * 16 + erow;
        int r1 = r0 + 8;
        float inv0 = 1.f / rsBase[(size_t)z * S + r0];
        float inv1 = 1.f / rsBase[(size_t)z * S + r1];
#pragma unroll
        for (int nt = 0; nt < 8; nt++) {
            int c0 = n0 + warpN + nt * 8 + ecol;
            float v0 = acc[mt][nt][0] * inv0, v1 = acc[mt][nt][1] * inv0;
            float v2 = acc[mt][nt][2] * inv1, v3 = acc[mt][nt][3] * inv1;
            uint32_t h0, l0, h1, l1;
            split2(v0, v1, h0, l0);
            split2(v2, v3, h1, l1);
            size_t o0 = (size_t)r0 * Dm + z * HD + c0;
            size_t o1 = (size_t)r1 * Dm + z * HD + c0;
            *(uint32_t*)&Coh[o0] = h0; *(uint32_t*)&Col[o0] = l0;
            *(uint32_t*)&Coh[o1] = h1; *(uint32_t*)&Col[o1] = l1;
        }
    }
}

// ---------------- fp32 -> bf16 hi/lo split (single) ----------------
__global__ void __launch_bounds__(256) split_kernel(
    const float* __restrict__ x, __nv_bfloat16* __restrict__ hi, __nv_bfloat16* __restrict__ lo)
{
    int i = (blockIdx.x * 256 + threadIdx.x) * 8;
    float f[8];
    *(float4*)&f[0] = *(const float4*)(x + i);
    *(float4*)&f[4] = *(const float4*)(x + i + 4);
    uint32_t h[4], l[4];
#pragma unroll
    for (int q = 0; q < 4; q++) split2(f[q * 2], f[q * 2 + 1], h[q], l[q]);
    *(uint4*)(hi + i) = make_uint4(h[0], h[1], h[2], h[3]);
    *(uint4*)(lo + i) = make_uint4(l[0], l[1], l[2], l[3]);
}

// ---------------- batched weight split (wq/wk/wv by z) ----------------
__global__ void __launch_bounds__(256) split3_kernel(
    const float* __restrict__ w0, const float* __restrict__ w1, const float* __restrict__ w2,
    __nv_bfloat16* __restrict__ base)
{
    const int z = blockIdx.z;
    const float* x = (z == 0) ? w0 : (z == 1) ? w1 : w2;
    __nv_bfloat16* hi = base + (size_t)z * 2 * Dm * Dm;
    __nv_bfloat16* lo = hi + (size_t)Dm * Dm;
    int i = (blockIdx.x * 256 + threadIdx.x) * 8;
    float f[8];
    *(float4*)&f[0] = *(const float4*)(x + i);
    *(float4*)&f[4] = *(const float4*)(x + i + 4);
    uint32_t h[4], l[4];
#pragma unroll
    for (int q = 0; q < 4; q++) split2(f[q * 2], f[q * 2 + 1], h[q], l[q]);
    *(uint4*)(hi + i) = make_uint4(h[0], h[1], h[2], h[3]);
    *(uint4*)(lo + i) = make_uint4(l[0], l[1], l[2], l[3]);
}

// ---------------- RoPE (fp32 in -> bf16 split out) ----------------
__global__ void __launch_bounds__(64) rope_split_kernel(const int* __restrict__ pos_ids)
{
    int hs = blockIdx.x;
    int h = hs / S, s = hs % S;
    int d = threadIdx.x;
    float posf = (float)pos_ids[s];
    float invf = powf(10000.f, -((float)d) / 64.f);
    float fr = posf * invf;
    float c = cosf(fr), sn = sinf(fr);
    size_t base = ((size_t)h * S + s) * HD;
    const float* Q = g_QKV;
    const float* K = g_QKV + (size_t)Hh * S * HD;
    float q1 = Q[base + d], q2 = Q[base + d + 64];
    float k1 = K[base + d], k2 = K[base + d + 64];
    float qa = q1 * c - q2 * sn, qb = q2 * c + q1 * sn;
    float ka = k1 * c - k2 * sn, kb = k2 * c + k1 * sn;
#define WR(arr_h, arr_l, off, v) do { \
        __nv_bfloat16 _hb = __float2bfloat16_rn(v); \
        arr_h[base + (off)] = _hb; \
        arr_l[base + (off)] = __float2bfloat16_rn((v) - __bfloat162float(_hb)); } while (0)
    WR(g_Qbh, g_Qbl, d, qa);
    WR(g_Qbh, g_Qbl, d + 64, qb);
    WR(g_Kbh, g_Kbl, d, ka);
    WR(g_Kbh, g_Kbl, d + 64, kb);
#undef WR
}

// ---------------- V transpose + split ----------------
__global__ void __launch_bounds__(256) vtrans_kernel()
{
    __shared__ float tile[32][33];
    int h = blockIdx.z, s0 = blockIdx.x * 32, d0 = blockIdx.y * 32;
    int tx = threadIdx.x & 31, ty = threadIdx.x >> 5;
    const float* Vb = g_QKV + (size_t)2 * Hh * S * HD + (size_t)h * S * HD;
#pragma unroll
    for (int i = 0; i < 4; i++)
        tile[ty * 4 + i][tx] = Vb[(size_t)(s0 + ty * 4 + i) * HD + d0 + tx];
    __syncthreads();
#pragma unroll
    for (int i = 0; i < 4; i++) {
        int d = d0 + ty * 4 + i;
        float v = tile[tx][ty * 4 + i];
        __nv_bfloat16 hb = __float2bfloat16_rn(v);
        g_VTh[((size_t)h * HD + d) * S + s0 + tx] = hb;
        g_VTl[((size_t)h * HD + d) * S + s0 + tx] = __float2bfloat16_rn(v - __bfloat162float(hb));
    }
}

// ---------------- softmax: triangular reads, exp-skip branches, full zero writes ----------------
__global__ void __launch_bounds__(256) softmax_kernel()
{
    int r = blockIdx.x, h = blockIdx.y, tid = threadIdx.x;
    float* row = g_scores + ((size_t)h * S + r) * S;
    float4* row4 = (float4*)row;
    const int n = r + 1;
    const int nv = (r >> 2) + 1;     // float4s containing any valid data
    __shared__ float sred[9];

    float4 v0 = make_float4(NEG_MIN_F, NEG_MIN_F, NEG_MIN_F, NEG_MIN_F), v1 = v0;
    if (tid < nv) v0 = row4[tid];
    if (tid + 256 < nv) v1 = row4[tid + 256];
    const int p0 = tid * 4, p1 = 1024 + tid * 4;
    float mx = NEG_MIN_F;
    if (p0 < n) {
        mx = fmaxf(mx, v0.x);
        mx = fmaxf(mx, (p0 + 1 < n) ? v0.y : NEG_MIN_F);
        mx = fmaxf(mx, (p0 + 2 < n) ? v0.z : NEG_MIN_F);
        mx = fmaxf(mx, (p0 + 3 < n) ? v0.w : NEG_MIN_F);
    }
    if (p1 < n) {
        mx = fmaxf(mx, v1.x);
        mx = fmaxf(mx, (p1 + 1 < n) ? v1.y : NEG_MIN_F);
        mx = fmaxf(mx, (p1 + 2 < n) ? v1.z : NEG_MIN_F);
        mx = fmaxf(mx, (p1 + 3 < n) ? v1.w : NEG_MIN_F);
    }
#pragma unroll
    for (int o = 16; o > 0; o >>= 1) mx = fmaxf(mx, __shfl_xor_sync(0xffffffffu, mx, o));
    if ((tid & 31) == 0) sred[tid >> 5] = mx;
    __syncthreads();
    if (tid == 0) { float m = sred[0]; for (int i = 1; i < 8; i++) m = fmaxf(m, sred[i]); sred[8] = m; }
    __syncthreads();
    mx = sred[8];
    __syncthreads();

    float4 e0 = make_float4(0.f, 0.f, 0.f, 0.f), e1 = e0;
    float loc = 0.f;
    if (p0 < n) {
        e0.x = __expf(v0.x - mx);
        e0.y = (p0 + 1 < n) ? __expf(v0.y - mx) : 0.f;
        e0.z = (p0 + 2 < n) ? __expf(v0.z - mx) : 0.f;
        e0.w = (p0 + 3 < n) ? __expf(v0.w - mx) : 0.f;
        loc += e0.x + e0.y + e0.z + e0.w;
    }
    if (p1 < n) {
        e1.x = __expf(v1.x - mx);
        e1.y = (p1 + 1 < n) ? __expf(v1.y - mx) : 0.f;
        e1.z = (p1 + 2 < n) ? __expf(v1.z - mx) : 0.f;
        e1.w = (p1 + 3 < n) ? __expf(v1.w - mx) : 0.f;
        loc += e1.x + e1.y + e1.z + e1.w;
    }
#pragma unroll
    for (int o = 16; o > 0; o >>= 1) loc += __shfl_xor_sync(0xffffffffu, loc, o);
    if ((tid & 31) == 0) sred[tid >> 5] = loc;
    __syncthreads();
    if (tid == 0) {
        float s2 = 0.f;
        for (int i = 0; i < 8; i++) s2 += sred[i];
        g_rownorm[h * S + r] = s2;
        g_rowsum[h * S + r] = s2;
    }

    row4[tid] = e0;
    row4[tid + 256] = e1;
}

// ---------------- eviction scan: 4-deep STATIC rotation (unroll-4), R15 reduction ----------------
__global__ void __launch_bounds__(256) scan_kernel()
{
    const int h = blockIdx.x, tid = threadIdx.x;
    const int lane = tid & 31, warp = tid >> 5;
    const float* sc = g_scores + (size_t)h * S * S;
    __shared__ float coefEff[CACHE];
    __shared__ uint4 sRed[2][8];
    __shared__ float sSum2[2][8];
    __shared__ float sInit[8];

#pragma unroll
    for (int i = 0; i < 8; i++) g_evict[h * S + tid + i * 256] = 0x7fffffff;

    for (int i = tid; i < CACHE; i += 256)
        coefEff[i] = powf(PENALTY, (float)(CACHE - 1 - i)) / g_rownorm[h * S + i];
    __syncthreads();

    float sel[8];
#pragma unroll
    for (int i = 0; i < 8; i++) sel[i] = 0.f;

    for (int rrow = WARM_START; rrow < CACHE; rrow++) {
        float cf = coefEff[rrow];
        if (cf != 0.f) {
            const float* rp = sc + (size_t)rrow * S + tid;
            sel[0] = fmaf(cf, rp[0],   sel[0]);
            sel[1] = fmaf(cf, rp[256], sel[1]);
        }
    }

    // static 4-row rotation: step t uses RA=R[t&3], RB=R[(t+1)&3]; reloads t+4 into RA
    float R0[8], R1[8], R2[8], R3[8];
    {
        const float* p0 = sc + (size_t)CACHE * S + tid;
#pragma unroll
        for (int i = 0; i < 8; i++) R0[i] = p0[i * 256];
        const float* p1 = sc + (size_t)(CACHE + 1) * S + tid;
#pragma unroll
        for (int i = 0; i < 8; i++) R1[i] = p1[i * 256];
        const float* p2 = sc + (size_t)(CACHE + 2) * S + tid;
#pragma unroll
        for (int i = 0; i < 8; i++) R2[i] = p2[i * 256];
        const float* p3 = sc + (size_t)(CACHE + 3) * S + tid;
#pragma unroll
        for (int i = 0; i < 8; i++) R3[i] = p3[i * 256];
    }
    float tot;
    {
        float loc = 0.f;
#pragma unroll
        for (int i = 0; i < 8; i++) loc += R0[i];
#pragma unroll
        for (int o = 16; o > 0; o >>= 1) loc += __shfl_xor_sync(0xffffffffu, loc, o);
        if (lane == 0) sInit[warp] = loc;
        __syncthreads();
        float s2 = 0.f;
#pragma unroll
        for (int w = 0; w < 8; w++) s2 += sInit[w];
        tot = s2;
    }

#define SCAN_STEP(t, RA, RB, BUF) do {                                          \
    const int lim = (t) - RECENT;                                               \
    const float inv = 1.0f / tot;                                               \
    unsigned long long key = ~0ull;                                             \
    float pay = 0.f, sg = 0.f;                                                  \
    _Pragma("unroll")                                                           \
    for (int i = 0; i < 8; i++) {                                               \
        bool keep = (sel[i] <= 1.0e30f);                                        \
        float c = keep ? RA[i] : 0.f;                                           \
        float ns = __fadd_rn(__fmul_rn(PENALTY, sel[i]), __fmul_rn(c, inv));    \
        sel[i] = ns;                                                            \
        float nv1 = RB[i];                                                      \
        sg += keep ? nv1 : 0.f;                                                 \
        int p = tid + (i << 8);                                                 \
        if (p <= lim) {                                                         \
            unsigned long long k2 =                                             \
                ((unsigned long long)__float_as_uint(ns) << 32) | (unsigned)p;  \
            if (k2 < key) { key = k2; pay = nv1; }                              \
        }                                                                       \
    }                                                                           \
    if ((t) + 4 < S) {                                                          \
        const float* rp = sc + (size_t)((t) + 4) * S + tid;                     \
        _Pragma("unroll")                                                       \
        for (int i = 0; i < 8; i++) RA[i] = rp[i * 256];                        \
    }                                                                           \
    float wsum = sg;                                                            \
    _Pragma("unroll")                                                           \
    for (int o = 8; o > 0; o >>= 1) wsum += __shfl_xor_sync(0xffffffffu, wsum, o); \
    uint32_t lv = (uint32_t)(key >> 32), lp = (uint32_t)key;                    \
    uint32_t vmin = __reduce_min_sync(0xffffffffu, lv);                         \
    uint32_t pmin = __reduce_min_sync(0xffffffffu, (lv == vmin) ? lp : 0xffffffffu); \
    float wpay = __shfl_sync(0xffffffffu, pay, (int)(pmin & 31));               \
    if (lane == 0)                                                              \
        sRed[BUF][warp] = make_uint4(vmin, pmin, __float_as_uint(wsum), __float_as_uint(wpay)); \
    if (lane == 16) sSum2[BUF][warp] = wsum;                                    \
    __syncthreads();                                                            \
    uint4 q0 = sRed[BUF][0];                                                    \
    unsigned long long gk = ((unsigned long long)q0.x << 32) | q0.y;            \
    float gs = __uint_as_float(q0.z) + sSum2[BUF][0];                           \
    float gpay = __uint_as_float(q0.w);                                         \
    _Pragma("unroll")                                                           \
    for (int w = 1; w < 8; w++) {                                               \
        uint4 q = sRed[BUF][w];                                                 \
        unsigned long long kk = ((unsigned long long)q.x << 32) | q.y;          \
        gs += __uint_as_float(q.z) + sSum2[BUF][w];                             \
        if (kk < gk) { gk = kk; gpay = __uint_as_float(q.w); }                  \
    }                                                                           \
    int mpos = (int)(gk & 0xffffffffu);                                         \
    tot = gs - gpay;                                                            \
    if (tid == 0) g_rowsum[h * S + (t) + 1] = tot;                              \
    if ((mpos & 255) == tid) {                                                  \
        sel[mpos >> 8] = __int_as_float(0x7f800000);                            \
        g_evict[h * S + mpos] = t;                                              \
    }                                                                           \
} while (0)

    // CACHE is even, so buf parity for steps tb+0..tb+3 is statically 0,1,0,1
    for (int tb = CACHE; tb < S - 1; tb += 4) {
        SCAN_STEP(tb, R0, R1, 0);
        if (tb + 1 < S - 1) SCAN_STEP(tb + 1, R1, R2, 1);
        if (tb + 2 < S - 1) SCAN_STEP(tb + 2, R2, R3, 0);
        if (tb + 3 < S - 1) SCAN_STEP(tb + 3, R3, R0, 1);
    }
#undef SCAN_STEP
}

// ---------------- launch ----------------
extern "C" void kernel_launch(void* const* d_in, const int* in_sizes, int n_in,
                              void* d_out, int out_size)
{
    (void)in_sizes; (void)n_in; (void)out_size;
    const float* hs  = (const float*)d_in[0];
    const int*   pos = (const int*)d_in[2];
    const float* wq  = (const float*)d_in[3];
    const float* wk  = (const float*)d_in[4];
    const float* wv  = (const float*)d_in[5];
    const float* wo  = (const float*)d_in[6];
    float* out = (float*)d_out;

    float *pQKV, *pS, *pRs;
    int* pEv;
    __nv_bfloat16 *pHSh, *pHSl, *pW, *pQh, *pQl, *pKh, *pKl, *pVTh, *pVTl, *pAOh, *pAOl;
    cudaGetSymbolAddress((void**)&pQKV, g_QKV);
    cudaGetSymbolAddress((void**)&pS,   g_scores);
    cudaGetSymbolAddress((void**)&pRs,  g_rowsum);
    cudaGetSymbolAddress((void**)&pEv,  g_evict);
    cudaGetSymbolAddress((void**)&pHSh, g_HSh);
    cudaGetSymbolAddress((void**)&pHSl, g_HSl);
    cudaGetSymbolAddress((void**)&pW,   g_Wsp);
    cudaGetSymbolAddress((void**)&pQh,  g_Qbh);
    cudaGetSymbolAddress((void**)&pQl,  g_Qbl);
    cudaGetSymbolAddress((void**)&pKh,  g_Kbh);
    cudaGetSymbolAddress((void**)&pKl,  g_Kbl);
    cudaGetSymbolAddress((void**)&pVTh, g_VTh);
    cudaGetSymbolAddress((void**)&pVTl, g_VTl);
    cudaGetSymbolAddress((void**)&pAOh, g_AOh);
    cudaGetSymbolAddress((void**)&pAOl, g_AOl);

    const size_t DD = (size_t)Dm * Dm;
    __nv_bfloat16* woh = pW + 6 * DD; __nv_bfloat16* wol = pW + 7 * DD;

    cudaFuncSetAttribute(cp_gemm<0>, cudaFuncAttributeMaxDynamicSharedMemorySize, G_SMEM);
    cudaFuncSetAttribute(cp_gemm<1>, cudaFuncAttributeMaxDynamicSharedMemorySize, G_SMEM);
    cudaFuncSetAttribute(cp_gemm<2>, cudaFuncAttributeMaxDynamicSharedMemorySize, G_SMEM);
    cudaFuncSetAttribute(pv_gemm,    cudaFuncAttributeMaxDynamicSharedMemorySize, PV_SMEM);

    const int splitGrid = (int)(DD / (256 * 8));
    split_kernel<<<splitGrid, 256>>>(hs, pHSh, pHSl);
    split3_kernel<<<dim3(splitGrid, 1, 3), 256>>>(wq, wk, wv, pW);
    split_kernel<<<splitGrid, 256>>>(wo, woh, wol);
    // slot 4 (profiled): merged QKV projection
    cp_gemm<1><<<dim3(16, 8, 3), 512, G_SMEM>>>(pHSh, pHSl, pW, pW + DD, pQKV,
        Dm, Dm, Dm, Dm, 0, 2 * DD, (size_t)Hh * S * HD);
    rope_split_kernel<<<Hh * S, 64>>>(pos);
    vtrans_kernel<<<dim3(S / 32, HD / 32, Hh), 256>>>();
    cp_gemm<2><<<dim3(16, 8, Hh), 512, G_SMEM>>>(pQh, pQl, pKh, pKl, pS,
        HD, HD, HD, S, (size_t)S * HD, (size_t)S * HD, (size_t)S * S);
    softmax_kernel<<<dim3(S, Hh), 256>>>();
    scan_kernel<<<Hh, 256>>>();
    pv_gemm<<<dim3(1, 16, Hh), 256, PV_SMEM>>>(pS, pVTh, pVTl, pAOh, pAOl,
        S, S, (size_t)S * S, (size_t)HD * S, pEv, pRs);
    cp_gemm<0><<<dim3(16, 8, 1), 512, G_SMEM>>>(pAOh, pAOl, woh, wol, out,
        Dm, Dm, Dm, Dm, 0, 0, 0);
}